// round 1
// baseline (speedup 1.0000x reference)
#include <cuda_runtime.h>
#include <cuda_bf16.h>
#include <math.h>

// Problem constants
#define B_    32
#define CIN   1280
#define HH    28
#define WW    28
#define HW    784            // 28*28
#define A_    9
#define C_    20
#define HID   128
#define OUTCH 65             // 5*A + C
#define M_    4096           // indices per list
#define MTOT  8192           // pos + neg rows
#define AHW   7056           // A*H*W

// Output layout (flat concat of the returned tuple)
#define OFF_CONF   0          // (8192,1)
#define OFF_OFFS   8192       // (4096,4)
#define OFF_CLASS  24576      // (4096,20)
#define OFF_IOU    106496     // (32,7056,64)

// Scratch (no cudaMalloc allowed)
__device__ float g_W1t[CIN * HID];     // [c][o] transposed W1
__device__ float g_H[MTOT * HID];      // gathered hidden activations (post leaky-relu)

// ---------------------------------------------------------------------------
// Kernel 1: transpose W1 (128x1280) -> W1t (1280x128) for coalesced GEMM loads
// ---------------------------------------------------------------------------
__global__ void transpose_w1_kernel(const float* __restrict__ W1) {
    __shared__ float tile[32][33];
    int c0 = blockIdx.x * 32;   // over CIN (40 tiles)
    int o0 = blockIdx.y * 32;   // over HID (4 tiles)
    int tx = threadIdx.x;       // 32
    int ty = threadIdx.y;       // 8
#pragma unroll
    for (int j = 0; j < 32; j += 8)
        tile[ty + j][tx] = W1[(o0 + ty + j) * CIN + c0 + tx];
    __syncthreads();
#pragma unroll
    for (int j = 0; j < 32; j += 8)
        g_W1t[(c0 + ty + j) * HID + o0 + tx] = tile[tx][ty + j];
}

// ---------------------------------------------------------------------------
// Kernel 2: gathered GEMM1.
//   For each of 8192 indices (4096 pos then 4096 neg):
//     x = features[b, :, h, w]   (K = 1280)
//     g_H[i] = leaky_relu( x @ W1^T + b1 )   (N = 128)
// Block tile: 32 indices x 128 hidden, K-chunks of 32. 256 threads, 4x4 regs.
// ---------------------------------------------------------------------------
__global__ void gemm1_gather_kernel(const float* __restrict__ feat,
                                    const float* __restrict__ b1,
                                    const int* __restrict__ pos,
                                    const int* __restrict__ neg) {
    __shared__ float As[32][36];    // [k][m] (padded)
    __shared__ float Bs[32][128];   // [k][n]
    __shared__ int   boff[32];

    const int i0 = blockIdx.x * 32;
    const int t  = threadIdx.x;

    if (t < 32) {
        int gi  = i0 + t;
        int idx = (gi < M_) ? pos[gi] : neg[gi - M_];
        int w   = idx % WW;
        int tmp = idx / WW;
        int h   = tmp % HH;
        tmp /= HH;               // tmp = b*A + a
        int b   = tmp / A_;
        boff[t] = b * (CIN * HW) + h * WW + w;
    }
    __syncthreads();

    const int mi = t & 31;          // A-load row
    const int kq = t >> 5;          // A-load k phase (0..7)
    const int n4 = (t & 31) * 4;    // B-load col
    const int m0 = (t >> 5) * 4;    // compute: rows m0..m0+3
    const int n0 = (t & 31) * 4;    // compute: cols n0..n0+3
    const int base = boff[mi];

    float acc[4][4];
#pragma unroll
    for (int m = 0; m < 4; m++)
#pragma unroll
        for (int n = 0; n < 4; n++) acc[m][n] = 0.0f;

    for (int k0 = 0; k0 < CIN; k0 += 32) {
#pragma unroll
        for (int jj = 0; jj < 4; jj++) {
            int k = kq + jj * 8;
            As[k][mi] = feat[base + (k0 + k) * HW];
            *(float4*)&Bs[k][n4] = *(const float4*)&g_W1t[(k0 + k) * HID + n4];
        }
        __syncthreads();
#pragma unroll
        for (int k = 0; k < 32; k++) {
            float4 av = *(const float4*)&As[k][m0];
            float4 bv = *(const float4*)&Bs[k][n0];
            float am[4] = {av.x, av.y, av.z, av.w};
            float bn[4] = {bv.x, bv.y, bv.z, bv.w};
#pragma unroll
            for (int m = 0; m < 4; m++)
#pragma unroll
                for (int n = 0; n < 4; n++) acc[m][n] += am[m] * bn[n];
        }
        __syncthreads();
    }

#pragma unroll
    for (int m = 0; m < 4; m++) {
#pragma unroll
        for (int n = 0; n < 4; n++) {
            float v = acc[m][n] + b1[n0 + n];
            v = (v > 0.0f) ? v : 0.01f * v;   // leaky relu
            g_H[(i0 + m0 + m) * HID + n0 + n] = v;
        }
    }
}

// ---------------------------------------------------------------------------
// Kernel 3: head. One warp per index.
//   pos i: conf (row 5a, sigmoid), offsets (rows 5a+1..5a+4, first two
//          sigmoid-0.5), class scores (rows 45..64)
//   neg i: conf only
// ---------------------------------------------------------------------------
__device__ __forceinline__ float sigmoidf_(float x) {
    return 1.0f / (1.0f + expf(-x));
}

__global__ void head_kernel(const float* __restrict__ W2,
                            const float* __restrict__ b2,
                            const int* __restrict__ pos,
                            const int* __restrict__ neg,
                            float* __restrict__ out) {
    __shared__ float hsh[8][128];
    int gw   = (blockIdx.x * blockDim.x + threadIdx.x) >> 5;
    int lane = threadIdx.x & 31;
    int wl   = (threadIdx.x >> 5);
    if (gw >= MTOT) return;

    const float* hrow = g_H + (size_t)gw * HID;
    hsh[wl][lane]      = hrow[lane];
    hsh[wl][lane + 32] = hrow[lane + 32];
    hsh[wl][lane + 64] = hrow[lane + 64];
    hsh[wl][lane + 96] = hrow[lane + 96];
    __syncwarp();

    int idx = (gw < M_) ? pos[gw] : neg[gw - M_];
    int a   = (idx / HW) % A_;

    if (gw < M_) {
        if (lane < 25) {
            int row = (lane < 5) ? (a * 5 + lane) : (45 + lane - 5);
            float s = b2[row];
            const float* wrow = W2 + row * HID;
#pragma unroll 8
            for (int c = 0; c < HID; c++) s += wrow[c] * hsh[wl][c];
            if (lane == 0) {
                out[OFF_CONF + gw] = sigmoidf_(s);
            } else if (lane <= 2) {
                out[OFF_OFFS + gw * 4 + (lane - 1)] = sigmoidf_(s) - 0.5f;
            } else if (lane <= 4) {
                out[OFF_OFFS + gw * 4 + (lane - 1)] = s;
            } else {
                out[OFF_CLASS + gw * 20 + (lane - 5)] = s;
            }
        }
    } else {
        int row = a * 5;
        float s = 0.0f;
        const float* wrow = W2 + row * HID;
        for (int c = lane; c < HID; c += 32) s += wrow[c] * hsh[wl][c];
#pragma unroll
        for (int o = 16; o; o >>= 1) s += __shfl_xor_sync(0xffffffffu, s, o);
        if (lane == 0) {
            s += b2[row];
            out[OFF_CONF + gw] = sigmoidf_(s);   // gw in [4096,8192) -> conf_neg slot
        }
    }
}

// ---------------------------------------------------------------------------
// Kernel 4: IoU matrix (B, A*H*W, 64). Block: 128 anchors x 64 boxes.
// Threads: 256 = 64 (n, fast/coalesced) x 4 (anchor lanes).
// ---------------------------------------------------------------------------
__global__ void iou_kernel(const float* __restrict__ grid,
                           const float* __restrict__ anc,
                           const float* __restrict__ bboxes,
                           float* __restrict__ out) {
    __shared__ float s_x1[64], s_y1[64], s_x2[64], s_y2[64], s_sb[64];
    const int b = blockIdx.y;
    const int t = threadIdx.x;

    if (t < 64) {
        const float* bb = bboxes + ((size_t)b * 64 + t) * 5;
        float x1 = bb[0], y1 = bb[1], x2 = bb[2], y2 = bb[3];
        s_x1[t] = x1; s_y1[t] = y1; s_x2[t] = x2; s_y2[t] = y2;
        float sb = (x2 - x1) * (y2 - y1);
        s_sb[t] = (x1 < 0.0f) ? 0.0f : sb;    // invalid -> forces iou=0 below
    }
    __syncthreads();

    const int n  = t & 63;
    const int jl = t >> 6;
    const int j0 = blockIdx.x * 128;

    const float bx1 = s_x1[n], by1 = s_y1[n], bx2 = s_x2[n], by2 = s_y2[n];
    const float sb  = s_sb[n];

    for (int jj = jl; jj < 128; jj += 4) {
        int j = j0 + jj;
        if (j >= AHW) break;
        int a = j / HW;
        int r = j - a * HW;
        int h = r / WW;
        int w = r - h * WW;
        float cx = grid[(((size_t)b * HH + h) * WW + w) * 2 + 0];
        float cy = grid[(((size_t)b * HH + h) * WW + w) * 2 + 1];
        float hw2 = anc[a * 2 + 0] * 0.5f;
        float hh2 = anc[a * 2 + 1] * 0.5f;
        float px1 = cx - hw2, py1 = cy - hh2, px2 = cx + hw2, py2 = cy + hh2;
        float sp  = (px2 - px1) * (py2 - py1);

        float ix1 = fmaxf(px1, bx1);
        float iy1 = fmaxf(py1, by1);
        float ix2 = fminf(px2, bx2);
        float iy2 = fminf(py2, by2);
        float si  = fmaxf(ix2 - ix1, 0.0f) * fmaxf(iy2 - iy1, 0.0f);
        float su  = sp + sb - si;

        float iou;
        if (su <= 0.0f || sp <= 0.0f || sb <= 0.0f) {
            iou = 0.0f;
        } else {
            iou = fmaxf(si / (su + 1e-8f), 0.0f);
        }
        out[OFF_IOU + ((size_t)b * AHW + j) * 64 + n] = iou;
    }
}

// ---------------------------------------------------------------------------
// Launch
// ---------------------------------------------------------------------------
extern "C" void kernel_launch(void* const* d_in, const int* in_sizes, int n_in,
                              void* d_out, int out_size) {
    const float* features = (const float*)d_in[0];
    const float* grid     = (const float*)d_in[1];
    const float* anc      = (const float*)d_in[2];
    const float* bboxes   = (const float*)d_in[3];
    const int*   pos      = (const int*)d_in[4];
    const int*   neg      = (const int*)d_in[5];
    const float* W1       = (const float*)d_in[6];
    const float* b1       = (const float*)d_in[7];
    const float* W2       = (const float*)d_in[8];
    const float* b2       = (const float*)d_in[9];
    float* out = (float*)d_out;

    // IoU is independent — launch first so it overlaps nothing but fills DRAM
    {
        dim3 g((AHW + 127) / 128, B_);
        iou_kernel<<<g, 256>>>(grid, anc, bboxes, out);
    }

    // W1 transpose for coalesced GEMM B loads
    {
        dim3 g(CIN / 32, HID / 32);
        dim3 blk(32, 8);
        transpose_w1_kernel<<<g, blk>>>(W1);
    }

    // Gathered hidden-layer GEMM (8192 x 1280 x 128)
    {
        gemm1_gather_kernel<<<MTOT / 32, 256>>>(features, b1, pos, neg);
    }

    // Head: one warp per index
    {
        head_kernel<<<MTOT / 8, 256>>>(W2, b2, pos, neg, out);
    }
}

// round 2
// speedup vs baseline: 1.2833x; 1.2833x over previous
#include <cuda_runtime.h>
#include <cuda_bf16.h>
#include <math.h>

// Problem constants
#define B_    32
#define CIN   1280
#define HH    28
#define WW    28
#define HW    784            // 28*28
#define A_    9
#define C_    20
#define HID   128
#define OUTCH 65             // 5*A + C
#define M_    4096           // indices per list
#define MTOT  8192           // pos + neg rows
#define AHW   7056           // A*H*W

// Output layout (flat concat of the returned tuple)
#define OFF_CONF   0          // (8192,1)
#define OFF_OFFS   8192       // (4096,4)
#define OFF_CLASS  24576      // (4096,20)
#define OFF_IOU    106496     // (32,7056,64)

// Scratch (no cudaMalloc allowed)
__device__ float g_W1t[CIN * HID];     // [c][o] transposed W1
__device__ float g_H[MTOT * HID];      // gathered hidden activations (post leaky-relu)

// ---------------------------------------------------------------------------
// Kernel 1: transpose W1 (128x1280) -> W1t (1280x128) for coalesced GEMM loads
// ---------------------------------------------------------------------------
__global__ void transpose_w1_kernel(const float* __restrict__ W1) {
    __shared__ float tile[32][33];
    int c0 = blockIdx.x * 32;   // over CIN (40 tiles)
    int o0 = blockIdx.y * 32;   // over HID (4 tiles)
    int tx = threadIdx.x;       // 32
    int ty = threadIdx.y;       // 8
#pragma unroll
    for (int j = 0; j < 32; j += 8)
        tile[ty + j][tx] = W1[(o0 + ty + j) * CIN + c0 + tx];
    __syncthreads();
#pragma unroll
    for (int j = 0; j < 32; j += 8)
        g_W1t[(c0 + ty + j) * HID + o0 + tx] = tile[tx][ty + j];
}

// ---------------------------------------------------------------------------
// Kernel 2: gathered GEMM1.
//   For each of 8192 indices (4096 pos then 4096 neg):
//     x = features[b, :, h, w]   (K = 1280)
//     g_H[i] = leaky_relu( x @ W1^T + b1 )   (N = 128)
// Block tile: 32 indices x 128 hidden, K-chunks of 32. 256 threads, 4x4 regs.
// ---------------------------------------------------------------------------
__global__ void gemm1_gather_kernel(const float* __restrict__ feat,
                                    const float* __restrict__ b1,
                                    const int* __restrict__ pos,
                                    const int* __restrict__ neg) {
    __shared__ float As[32][36];    // [k][m] (padded)
    __shared__ float Bs[32][128];   // [k][n]
    __shared__ int   boff[32];

    const int i0 = blockIdx.x * 32;
    const int t  = threadIdx.x;

    if (t < 32) {
        int gi  = i0 + t;
        int idx = (gi < M_) ? pos[gi] : neg[gi - M_];
        int w   = idx % WW;
        int tmp = idx / WW;
        int h   = tmp % HH;
        tmp /= HH;               // tmp = b*A + a
        int b   = tmp / A_;
        boff[t] = b * (CIN * HW) + h * WW + w;
    }
    __syncthreads();

    const int mi = t & 31;          // A-load row
    const int kq = t >> 5;          // A-load k phase (0..7)
    const int n4 = (t & 31) * 4;    // B-load col
    const int m0 = (t >> 5) * 4;    // compute: rows m0..m0+3
    const int n0 = (t & 31) * 4;    // compute: cols n0..n0+3
    const int base = boff[mi];

    float acc[4][4];
#pragma unroll
    for (int m = 0; m < 4; m++)
#pragma unroll
        for (int n = 0; n < 4; n++) acc[m][n] = 0.0f;

    for (int k0 = 0; k0 < CIN; k0 += 32) {
#pragma unroll
        for (int jj = 0; jj < 4; jj++) {
            int k = kq + jj * 8;
            As[k][mi] = feat[base + (k0 + k) * HW];
            *(float4*)&Bs[k][n4] = *(const float4*)&g_W1t[(k0 + k) * HID + n4];
        }
        __syncthreads();
#pragma unroll
        for (int k = 0; k < 32; k++) {
            float4 av = *(const float4*)&As[k][m0];
            float4 bv = *(const float4*)&Bs[k][n0];
            float am[4] = {av.x, av.y, av.z, av.w};
            float bn[4] = {bv.x, bv.y, bv.z, bv.w};
#pragma unroll
            for (int m = 0; m < 4; m++)
#pragma unroll
                for (int n = 0; n < 4; n++) acc[m][n] += am[m] * bn[n];
        }
        __syncthreads();
    }

#pragma unroll
    for (int m = 0; m < 4; m++) {
#pragma unroll
        for (int n = 0; n < 4; n++) {
            float v = acc[m][n] + b1[n0 + n];
            v = (v > 0.0f) ? v : 0.01f * v;   // leaky relu
            g_H[(i0 + m0 + m) * HID + n0 + n] = v;
        }
    }
}

// ---------------------------------------------------------------------------
// Kernel 3: head. One warp per index, channel-parallel.
//   Lane l owns channels [4l, 4l+4) via float4 loads (coalesced, W2 L1-hot);
//   each output row = 1 LDG.128 + 4 FFMA + shfl_xor tree reduction.
//   pos i: conf (row 5a, sigmoid), offsets (rows 5a+1..5a+4, first two
//          sigmoid-0.5), class scores (rows 45..64)
//   neg i: conf only
// ---------------------------------------------------------------------------
__device__ __forceinline__ float sigmoidf_(float x) {
    return 1.0f / (1.0f + expf(-x));
}

__global__ void head_kernel(const float* __restrict__ W2,
                            const float* __restrict__ b2,
                            const int* __restrict__ pos,
                            const int* __restrict__ neg,
                            float* __restrict__ out) {
    int gw   = (blockIdx.x * blockDim.x + threadIdx.x) >> 5;
    int lane = threadIdx.x & 31;
    if (gw >= MTOT) return;

    // h row: lane l holds channels 4l..4l+3 (coalesced 512B per warp)
    float4 hv = ((const float4*)(g_H + (size_t)gw * HID))[lane];

    int idx = (gw < M_) ? pos[gw] : neg[gw - M_];
    int a   = (idx / HW) % A_;

    if (gw < M_) {
#pragma unroll
        for (int r = 0; r < 25; r++) {
            int row = (r < 5) ? (a * 5 + r) : (40 + r);   // 45 + (r-5)
            float4 wv = ((const float4*)(W2 + row * HID))[lane];
            float s = wv.x * hv.x + wv.y * hv.y + wv.z * hv.z + wv.w * hv.w;
#pragma unroll
            for (int o = 16; o; o >>= 1) s += __shfl_xor_sync(0xffffffffu, s, o);
            if (lane == 0) {
                s += b2[row];
                if (r == 0) {
                    out[OFF_CONF + gw] = sigmoidf_(s);
                } else if (r <= 2) {
                    out[OFF_OFFS + gw * 4 + (r - 1)] = sigmoidf_(s) - 0.5f;
                } else if (r <= 4) {
                    out[OFF_OFFS + gw * 4 + (r - 1)] = s;
                } else {
                    out[OFF_CLASS + gw * 20 + (r - 5)] = s;
                }
            }
        }
    } else {
        int row = a * 5;
        float4 wv = ((const float4*)(W2 + row * HID))[lane];
        float s = wv.x * hv.x + wv.y * hv.y + wv.z * hv.z + wv.w * hv.w;
#pragma unroll
        for (int o = 16; o; o >>= 1) s += __shfl_xor_sync(0xffffffffu, s, o);
        if (lane == 0) {
            out[OFF_CONF + gw] = sigmoidf_(s + b2[row]);  // gw in [4096,8192)
        }
    }
}

// ---------------------------------------------------------------------------
// Kernel 4: IoU matrix (B, A*H*W, 64). Block: 128 anchors x 64 boxes.
// Threads: 256 = 64 (n, fast/coalesced) x 4 (anchor lanes).
// ---------------------------------------------------------------------------
__global__ void iou_kernel(const float* __restrict__ grid,
                           const float* __restrict__ anc,
                           const float* __restrict__ bboxes,
                           float* __restrict__ out) {
    __shared__ float s_x1[64], s_y1[64], s_x2[64], s_y2[64], s_sb[64];
    const int b = blockIdx.y;
    const int t = threadIdx.x;

    if (t < 64) {
        const float* bb = bboxes + ((size_t)b * 64 + t) * 5;
        float x1 = bb[0], y1 = bb[1], x2 = bb[2], y2 = bb[3];
        s_x1[t] = x1; s_y1[t] = y1; s_x2[t] = x2; s_y2[t] = y2;
        float sb = (x2 - x1) * (y2 - y1);
        s_sb[t] = (x1 < 0.0f) ? 0.0f : sb;    // invalid -> forces iou=0 below
    }
    __syncthreads();

    const int n  = t & 63;
    const int jl = t >> 6;
    const int j0 = blockIdx.x * 128;

    const float bx1 = s_x1[n], by1 = s_y1[n], bx2 = s_x2[n], by2 = s_y2[n];
    const float sb  = s_sb[n];

    for (int jj = jl; jj < 128; jj += 4) {
        int j = j0 + jj;
        if (j >= AHW) break;
        int a = j / HW;
        int r = j - a * HW;
        int h = r / WW;
        int w = r - h * WW;
        float cx = grid[(((size_t)b * HH + h) * WW + w) * 2 + 0];
        float cy = grid[(((size_t)b * HH + h) * WW + w) * 2 + 1];
        float hw2 = anc[a * 2 + 0] * 0.5f;
        float hh2 = anc[a * 2 + 1] * 0.5f;
        float px1 = cx - hw2, py1 = cy - hh2, px2 = cx + hw2, py2 = cy + hh2;
        float sp  = (px2 - px1) * (py2 - py1);

        float ix1 = fmaxf(px1, bx1);
        float iy1 = fmaxf(py1, by1);
        float ix2 = fminf(px2, bx2);
        float iy2 = fminf(py2, by2);
        float si  = fmaxf(ix2 - ix1, 0.0f) * fmaxf(iy2 - iy1, 0.0f);
        float su  = sp + sb - si;

        float iou;
        if (su <= 0.0f || sp <= 0.0f || sb <= 0.0f) {
            iou = 0.0f;
        } else {
            iou = fmaxf(si / (su + 1e-8f), 0.0f);
        }
        out[OFF_IOU + ((size_t)b * AHW + j) * 64 + n] = iou;
    }
}

// ---------------------------------------------------------------------------
// Launch
// ---------------------------------------------------------------------------
extern "C" void kernel_launch(void* const* d_in, const int* in_sizes, int n_in,
                              void* d_out, int out_size) {
    const float* features = (const float*)d_in[0];
    const float* grid     = (const float*)d_in[1];
    const float* anc      = (const float*)d_in[2];
    const float* bboxes   = (const float*)d_in[3];
    const int*   pos      = (const int*)d_in[4];
    const int*   neg      = (const int*)d_in[5];
    const float* W1       = (const float*)d_in[6];
    const float* b1       = (const float*)d_in[7];
    const float* W2       = (const float*)d_in[8];
    const float* b2       = (const float*)d_in[9];
    float* out = (float*)d_out;

    // IoU is independent — launch first
    {
        dim3 g((AHW + 127) / 128, B_);
        iou_kernel<<<g, 256>>>(grid, anc, bboxes, out);
    }

    // W1 transpose for coalesced GEMM B loads
    {
        dim3 g(CIN / 32, HID / 32);
        dim3 blk(32, 8);
        transpose_w1_kernel<<<g, blk>>>(W1);
    }

    // Gathered hidden-layer GEMM (8192 x 1280 x 128)
    {
        gemm1_gather_kernel<<<MTOT / 32, 256>>>(features, b1, pos, neg);
    }

    // Head: one warp per index
    {
        head_kernel<<<MTOT / 8, 256>>>(W2, b2, pos, neg, out);
    }
}

// round 4
// speedup vs baseline: 1.3661x; 1.0645x over previous
#include <cuda_runtime.h>
#include <cuda_bf16.h>
#include <mma.h>
#include <math.h>
#include <stdint.h>

using namespace nvcuda;

// ---------------- problem constants ----------------
#define B_    32
#define CIN   1280
#define HH    28
#define WW    28
#define HW    784
#define A_    9
#define HID   128
#define M_    4096
#define MTOT  8192
#define AHW   7056
#define NPOS  (B_ * HW)        // 25088

// output layout
#define OFF_CONF   0
#define OFF_OFFS   8192
#define OFF_CLASS  24576
#define OFF_IOU    106496

// ---------------- scratch (__device__ globals; no cudaMalloc) ----------------
__device__ __nv_bfloat16 g_fT_hi[(size_t)NPOS * CIN];   // [b*HW+p][k]
__device__ __nv_bfloat16 g_fT_lo[(size_t)NPOS * CIN];
__device__ __nv_bfloat16 g_W1hi[HID * CIN];             // [n][k] (as W1)
__device__ __nv_bfloat16 g_W1lo[HID * CIN];
__device__ float g_H[MTOT * HID];                       // hidden per gathered slot

// ---------------------------------------------------------------------------
// Kernel A: W1 -> bf16 hi/lo split
// ---------------------------------------------------------------------------
__global__ void w1_split_kernel(const float* __restrict__ W1) {
    int i = blockIdx.x * blockDim.x + threadIdx.x;
    if (i >= HID * CIN) return;
    float v = W1[i];
    __nv_bfloat16 h = __float2bfloat16(v);
    g_W1hi[i] = h;
    g_W1lo[i] = __float2bfloat16(v - __bfloat162float(h));
}

// ---------------------------------------------------------------------------
// Kernel B: transpose features [B,C,HW] -> featT [B*HW, C] with bf16 split.
// 32x32 smem tiles, coalesced reads (along pos) and writes (along k).
// grid: (ceil(HW/32)=25, CIN/32=40, B)
// ---------------------------------------------------------------------------
__global__ void transpose_split_kernel(const float* __restrict__ feat) {
    __shared__ float tile[32][33];
    const int p0 = blockIdx.x * 32;
    const int k0 = blockIdx.y * 32;
    const int b  = blockIdx.z;
    const int tx = threadIdx.x;   // 32
    const int ty = threadIdx.y;   // 8

    const int p = p0 + tx;
#pragma unroll
    for (int jj = 0; jj < 4; jj++) {
        int kk = ty + jj * 8;
        tile[kk][tx] = (p < HW)
            ? feat[((size_t)b * CIN + (k0 + kk)) * HW + p] : 0.0f;
    }
    __syncthreads();

    const int k = k0 + tx;
#pragma unroll
    for (int jj = 0; jj < 4; jj++) {
        int pp = p0 + ty + jj * 8;
        if (pp < HW) {
            float v = tile[tx][ty + jj * 8];
            __nv_bfloat16 h = __float2bfloat16(v);
            size_t o = (size_t)(b * HW + pp) * CIN + k;
            g_fT_hi[o] = h;
            g_fT_lo[o] = __float2bfloat16(v - __bfloat162float(h));
        }
    }
}

// ---------------------------------------------------------------------------
// Kernel C: gathered WMMA GEMM.
//   g_H[i][n] = leaky( sum_k featT[row(i)][k] * W1[n][k] + b1[n] )
// Block: 64 gathered rows x 128 cols, 8 warps (4x2), K-chunks of 64.
// 3-term bf16 split, fp32 accum.
// ---------------------------------------------------------------------------
#define LDA 72
#define LDB 72
#define LDS_STAGE 132
// smem element offsets (bf16 units)
#define SA_HI 0
#define SA_LO (64 * LDA)              // 4608
#define SB_HI (2 * 64 * LDA)          // 9216
#define SB_LO (2 * 64 * LDA + 128 * LDB)
#define SMEM_ELEMS (2 * 64 * LDA + 2 * 128 * LDB)   // 27648 bf16 = 55296 B
#define SMEM_GEMM_BYTES (SMEM_ELEMS * 2)

extern __shared__ __nv_bfloat16 smem_g[];

__global__ void __launch_bounds__(256, 1)
gemm_wmma_kernel(const int* __restrict__ pos,
                 const int* __restrict__ neg,
                 const float* __restrict__ b1) {
    __shared__ int srow[64];

    const int t    = threadIdx.x;
    const int wid  = t >> 5;
    const int i0   = blockIdx.x * 64;

    if (t < 64) {
        int gi  = i0 + t;
        int idx = (gi < M_) ? pos[gi] : neg[gi - M_];
        int p   = idx % HW;
        int b   = idx / (HW * A_);
        srow[t] = b * HW + p;
    }
    __syncthreads();

    const int wr = wid >> 1;          // warp row tile (0..3) -> rows wr*16
    const int wc = wid & 1;           // warp col half (0..1) -> cols wc*64

    wmma::fragment<wmma::accumulator, 16, 16, 16, float> acc[4];
#pragma unroll
    for (int nt = 0; nt < 4; nt++) wmma::fill_fragment(acc[nt], 0.0f);

    for (int k0 = 0; k0 < CIN; k0 += 64) {
        // ---- stage A (gathered rows) : 64 rows x 64 k, hi & lo ----
        // 512 uint4 per array; thread t does q = t, t+256
#pragma unroll
        for (int h = 0; h < 2; h++) {
            int q   = t + h * 256;
            int row = q >> 3;
            int j   = q & 7;          // uint4 index within row (8 bf16 each)
            size_t src = (size_t)srow[row] * CIN + k0 + j * 8;
            *(uint4*)&smem_g[SA_HI + row * LDA + j * 8] = *(const uint4*)&g_fT_hi[src];
            *(uint4*)&smem_g[SA_LO + row * LDA + j * 8] = *(const uint4*)&g_fT_lo[src];
        }
        // ---- stage B (W1 slice) : 128 n x 64 k, hi & lo ----
        // 1024 uint4 per array; thread t does q = t + i*256
#pragma unroll
        for (int h = 0; h < 4; h++) {
            int q = t + h * 256;
            int n = q >> 3;
            int j = q & 7;
            size_t src = (size_t)n * CIN + k0 + j * 8;
            *(uint4*)&smem_g[SB_HI + n * LDB + j * 8] = *(const uint4*)&g_W1hi[src];
            *(uint4*)&smem_g[SB_LO + n * LDB + j * 8] = *(const uint4*)&g_W1lo[src];
        }
        __syncthreads();

#pragma unroll
        for (int ks = 0; ks < 4; ks++) {
            wmma::fragment<wmma::matrix_a, 16, 16, 16, __nv_bfloat16, wmma::row_major> a_hi, a_lo;
            wmma::load_matrix_sync(a_hi, &smem_g[SA_HI + (wr * 16) * LDA + ks * 16], LDA);
            wmma::load_matrix_sync(a_lo, &smem_g[SA_LO + (wr * 16) * LDA + ks * 16], LDA);
#pragma unroll
            for (int nt = 0; nt < 4; nt++) {
                int n = wc * 64 + nt * 16;
                wmma::fragment<wmma::matrix_b, 16, 16, 16, __nv_bfloat16, wmma::col_major> b_hi, b_lo;
                wmma::load_matrix_sync(b_hi, &smem_g[SB_HI + n * LDB + ks * 16], LDB);
                wmma::load_matrix_sync(b_lo, &smem_g[SB_LO + n * LDB + ks * 16], LDB);
                wmma::mma_sync(acc[nt], a_hi, b_hi, acc[nt]);
                wmma::mma_sync(acc[nt], a_hi, b_lo, acc[nt]);
                wmma::mma_sync(acc[nt], a_lo, b_hi, acc[nt]);
            }
        }
        __syncthreads();
    }

    // ---- epilogue: stage accum in smem, bias + leaky, store g_H ----
    float* stage = (float*)smem_g;    // 64 x LDS_STAGE floats (reuses tiles)
#pragma unroll
    for (int nt = 0; nt < 4; nt++) {
        wmma::store_matrix_sync(&stage[(wr * 16) * LDS_STAGE + wc * 64 + nt * 16],
                                acc[nt], LDS_STAGE, wmma::mem_row_major);
    }
    __syncthreads();

    for (int i = t; i < 64 * 32; i += 256) {
        int row = i >> 5;
        int c4  = (i & 31) * 4;
        float4 v = *(float4*)&stage[row * LDS_STAGE + c4];
        v.x += b1[c4 + 0]; v.y += b1[c4 + 1]; v.z += b1[c4 + 2]; v.w += b1[c4 + 3];
        v.x = (v.x > 0.f) ? v.x : 0.01f * v.x;
        v.y = (v.y > 0.f) ? v.y : 0.01f * v.y;
        v.z = (v.z > 0.f) ? v.z : 0.01f * v.z;
        v.w = (v.w > 0.f) ? v.w : 0.01f * v.w;
        *(float4*)&g_H[(size_t)(i0 + row) * HID + c4] = v;
    }
}

// ---------------------------------------------------------------------------
// Head: one warp per index, channel-parallel (reads g_H by slot)
// ---------------------------------------------------------------------------
__device__ __forceinline__ float sigmoidf_(float x) {
    return 1.0f / (1.0f + expf(-x));
}

__global__ void head_kernel(const float* __restrict__ W2,
                            const float* __restrict__ b2,
                            const int* __restrict__ pos,
                            const int* __restrict__ neg,
                            float* __restrict__ out) {
    int gw   = (blockIdx.x * blockDim.x + threadIdx.x) >> 5;
    int lane = threadIdx.x & 31;
    if (gw >= MTOT) return;

    float4 hv = ((const float4*)(g_H + (size_t)gw * HID))[lane];

    int idx = (gw < M_) ? pos[gw] : neg[gw - M_];
    int a   = (idx / HW) % A_;

    if (gw < M_) {
#pragma unroll
        for (int r = 0; r < 25; r++) {
            int row = (r < 5) ? (a * 5 + r) : (40 + r);
            float4 wv = ((const float4*)(W2 + row * HID))[lane];
            float s = wv.x * hv.x + wv.y * hv.y + wv.z * hv.z + wv.w * hv.w;
#pragma unroll
            for (int o = 16; o; o >>= 1) s += __shfl_xor_sync(0xffffffffu, s, o);
            if (lane == 0) {
                s += b2[row];
                if (r == 0) {
                    out[OFF_CONF + gw] = sigmoidf_(s);
                } else if (r <= 2) {
                    out[OFF_OFFS + gw * 4 + (r - 1)] = sigmoidf_(s) - 0.5f;
                } else if (r <= 4) {
                    out[OFF_OFFS + gw * 4 + (r - 1)] = s;
                } else {
                    out[OFF_CLASS + gw * 20 + (r - 5)] = s;
                }
            }
        }
    } else {
        int row = a * 5;
        float4 wv = ((const float4*)(W2 + row * HID))[lane];
        float s = wv.x * hv.x + wv.y * hv.y + wv.z * hv.z + wv.w * hv.w;
#pragma unroll
        for (int o = 16; o; o >>= 1) s += __shfl_xor_sync(0xffffffffu, s, o);
        if (lane == 0) {
            out[OFF_CONF + gw] = sigmoidf_(s + b2[row]);
        }
    }
}

// ---------------------------------------------------------------------------
// IoU matrix (unchanged)
// ---------------------------------------------------------------------------
__global__ void iou_kernel(const float* __restrict__ grid,
                           const float* __restrict__ anc,
                           const float* __restrict__ bboxes,
                           float* __restrict__ out) {
    __shared__ float s_x1[64], s_y1[64], s_x2[64], s_y2[64], s_sb[64];
    const int b = blockIdx.y;
    const int t = threadIdx.x;

    if (t < 64) {
        const float* bb = bboxes + ((size_t)b * 64 + t) * 5;
        float x1 = bb[0], y1 = bb[1], x2 = bb[2], y2 = bb[3];
        s_x1[t] = x1; s_y1[t] = y1; s_x2[t] = x2; s_y2[t] = y2;
        float sb = (x2 - x1) * (y2 - y1);
        s_sb[t] = (x1 < 0.0f) ? 0.0f : sb;
    }
    __syncthreads();

    const int n  = t & 63;
    const int jl = t >> 6;
    const int j0 = blockIdx.x * 128;

    const float bx1 = s_x1[n], by1 = s_y1[n], bx2 = s_x2[n], by2 = s_y2[n];
    const float sb  = s_sb[n];

    for (int jj = jl; jj < 128; jj += 4) {
        int j = j0 + jj;
        if (j >= AHW) break;
        int a = j / HW;
        int r = j - a * HW;
        int h = r / WW;
        int w = r - h * WW;
        float cx = grid[(((size_t)b * HH + h) * WW + w) * 2 + 0];
        float cy = grid[(((size_t)b * HH + h) * WW + w) * 2 + 1];
        float hw2 = anc[a * 2 + 0] * 0.5f;
        float hh2 = anc[a * 2 + 1] * 0.5f;
        float px1 = cx - hw2, py1 = cy - hh2, px2 = cx + hw2, py2 = cy + hh2;
        float sp  = (px2 - px1) * (py2 - py1);

        float ix1 = fmaxf(px1, bx1);
        float iy1 = fmaxf(py1, by1);
        float ix2 = fminf(px2, bx2);
        float iy2 = fminf(py2, by2);
        float si  = fmaxf(ix2 - ix1, 0.0f) * fmaxf(iy2 - iy1, 0.0f);
        float su  = sp + sb - si;

        float iou;
        if (su <= 0.0f || sp <= 0.0f || sb <= 0.0f) {
            iou = 0.0f;
        } else {
            iou = fmaxf(si / (su + 1e-8f), 0.0f);
        }
        out[OFF_IOU + ((size_t)b * AHW + j) * 64 + n] = iou;
    }
}

// ---------------------------------------------------------------------------
// Launch
// ---------------------------------------------------------------------------
extern "C" void kernel_launch(void* const* d_in, const int* in_sizes, int n_in,
                              void* d_out, int out_size) {
    const float* features = (const float*)d_in[0];
    const float* grid     = (const float*)d_in[1];
    const float* anc      = (const float*)d_in[2];
    const float* bboxes   = (const float*)d_in[3];
    const int*   pos      = (const int*)d_in[4];
    const int*   neg      = (const int*)d_in[5];
    const float* W1       = (const float*)d_in[6];
    const float* b1       = (const float*)d_in[7];
    const float* W2       = (const float*)d_in[8];
    const float* b2       = (const float*)d_in[9];
    float* out = (float*)d_out;

    // IoU (independent of everything else)
    {
        dim3 g((AHW + 127) / 128, B_);
        iou_kernel<<<g, 256>>>(grid, anc, bboxes, out);
    }

    // W1 bf16 split (tiny)
    {
        int n = HID * CIN;
        w1_split_kernel<<<(n + 255) / 256, 256>>>(W1);
    }

    // Feature transpose + bf16 split (coalesced both sides)
    {
        dim3 g((HW + 31) / 32, CIN / 32, B_);
        dim3 blk(32, 8);
        transpose_split_kernel<<<g, blk>>>(features);
    }

    // Gathered WMMA GEMM
    {
        cudaFuncSetAttribute(gemm_wmma_kernel,
                             cudaFuncAttributeMaxDynamicSharedMemorySize,
                             SMEM_GEMM_BYTES);
        gemm_wmma_kernel<<<MTOT / 64, 256, SMEM_GEMM_BYTES>>>(pos, neg, b1);
    }

    // Head
    {
        head_kernel<<<MTOT / 8, 256>>>(W2, b2, pos, neg, out);
    }
}

// round 5
// speedup vs baseline: 1.7774x; 1.3011x over previous
#include <cuda_runtime.h>
#include <cuda_bf16.h>
#include <mma.h>
#include <math.h>
#include <stdint.h>

using namespace nvcuda;

// ---------------- problem constants ----------------
#define B_    32
#define CIN   1280
#define HH    28
#define WW    28
#define HW    784
#define A_    9
#define HID   128
#define M_    4096
#define MTOT  8192
#define AHW   7056
#define NPOS  (B_ * HW)        // 25088

// output layout
#define OFF_CONF   0
#define OFF_OFFS   8192
#define OFF_CLASS  24576
#define OFF_IOU    106496

// ---------------- scratch (__device__ globals; no cudaMalloc) ----------------
__device__ __nv_bfloat16 g_fT_hi[(size_t)NPOS * CIN];   // [b*HW+p][k]
__device__ __nv_bfloat16 g_fT_lo[(size_t)NPOS * CIN];
__device__ __nv_bfloat16 g_W1hi[HID * CIN];             // [n][k]
__device__ __nv_bfloat16 g_W1lo[HID * CIN];
__device__ float g_H[MTOT * HID];
__device__ unsigned char g_flag[NPOS];                  // zero-init; marking idempotent

// ---------------- helpers ----------------
__device__ __forceinline__ uint32_t smem_u32(const void* p) {
    uint32_t a;
    asm("{ .reg .u64 t; cvta.to.shared.u64 t, %1; cvt.u32.u64 %0, t; }"
        : "=r"(a) : "l"(p));
    return a;
}
__device__ __forceinline__ uint32_t PK(__nv_bfloat16 a, __nv_bfloat16 b) {
    unsigned short ua = *(unsigned short*)&a;
    unsigned short ub = *(unsigned short*)&b;
    return (uint32_t)ua | ((uint32_t)ub << 16);
}
__device__ __forceinline__ void cpa16(uint32_t dst, const void* src) {
    asm volatile("cp.async.ca.shared.global [%0], [%1], 16;" :: "r"(dst), "l"(src));
}
#define CP_COMMIT() asm volatile("cp.async.commit_group;" ::: "memory")
#define CP_WAIT0()  asm volatile("cp.async.wait_group 0;" ::: "memory")
#define CP_WAIT1()  asm volatile("cp.async.wait_group 1;" ::: "memory")

// ---------------------------------------------------------------------------
// Kernel 0: mark gathered rows (idempotent across replays; g_flag zero-init)
// ---------------------------------------------------------------------------
__global__ void mark_kernel(const int* __restrict__ pos,
                            const int* __restrict__ neg) {
    int i = blockIdx.x * blockDim.x + threadIdx.x;
    if (i >= MTOT) return;
    int idx = (i < M_) ? pos[i] : neg[i - M_];
    int p = idx % HW;
    int b = idx / (HW * A_);
    g_flag[b * HW + p] = 1;
}

// ---------------------------------------------------------------------------
// Kernel 1: fused prep = w1 split  +  IoU  +  flag-gated transpose/split
//   blocks [0,160): w1 split (float4)
//   blocks [160,1952): iou (56 x 32)
//   blocks [1952,33952): transpose (25 x 40 x 32)
// ---------------------------------------------------------------------------
#define W1_BLKS  160
#define IOU_BLKS (56 * 32)
#define TR_BLKS  (25 * 40 * 32)
#define PREP_BLKS (W1_BLKS + IOU_BLKS + TR_BLKS)

__global__ void __launch_bounds__(256)
prep_kernel(const float* __restrict__ feat,
            const float* __restrict__ W1,
            const float* __restrict__ grid,
            const float* __restrict__ anc,
            const float* __restrict__ bboxes,
            float* __restrict__ out) {
    const int bid = blockIdx.x;
    const int t   = threadIdx.x;

    if (bid < W1_BLKS) {
        // ---- W1 bf16 hi/lo split ----
        int i4 = bid * 256 + t;             // float4 index; 160*256*4 = 163840
        const float4 v = ((const float4*)W1)[i4];
        __nv_bfloat16 h0 = __float2bfloat16(v.x), h1 = __float2bfloat16(v.y);
        __nv_bfloat16 h2 = __float2bfloat16(v.z), h3 = __float2bfloat16(v.w);
        ((uint2*)g_W1hi)[i4] = make_uint2(PK(h0, h1), PK(h2, h3));
        ((uint2*)g_W1lo)[i4] = make_uint2(
            PK(__float2bfloat16(v.x - __bfloat162float(h0)),
               __float2bfloat16(v.y - __bfloat162float(h1))),
            PK(__float2bfloat16(v.z - __bfloat162float(h2)),
               __float2bfloat16(v.w - __bfloat162float(h3))));
        return;
    }

    if (bid < W1_BLKS + IOU_BLKS) {
        // ---- IoU ----
        __shared__ float s_x1[64], s_y1[64], s_x2[64], s_y2[64], s_sb[64];
        int r  = bid - W1_BLKS;
        int bx = r % 56;
        int b  = r / 56;

        if (t < 64) {
            const float* bb = bboxes + ((size_t)b * 64 + t) * 5;
            float x1 = bb[0], y1 = bb[1], x2 = bb[2], y2 = bb[3];
            s_x1[t] = x1; s_y1[t] = y1; s_x2[t] = x2; s_y2[t] = y2;
            float sb = (x2 - x1) * (y2 - y1);
            s_sb[t] = (x1 < 0.0f) ? 0.0f : sb;
        }
        __syncthreads();

        const int n  = t & 63;
        const int jl = t >> 6;
        const int j0 = bx * 128;
        const float bx1 = s_x1[n], by1 = s_y1[n], bx2 = s_x2[n], by2 = s_y2[n];
        const float sb  = s_sb[n];

        for (int jj = jl; jj < 128; jj += 4) {
            int j = j0 + jj;
            if (j >= AHW) break;
            int a = j / HW;
            int rr = j - a * HW;
            int h = rr / WW;
            int w = rr - h * WW;
            float cx = grid[(((size_t)b * HH + h) * WW + w) * 2 + 0];
            float cy = grid[(((size_t)b * HH + h) * WW + w) * 2 + 1];
            float hw2 = anc[a * 2 + 0] * 0.5f;
            float hh2 = anc[a * 2 + 1] * 0.5f;
            float px1 = cx - hw2, py1 = cy - hh2, px2 = cx + hw2, py2 = cy + hh2;
            float sp  = (px2 - px1) * (py2 - py1);
            float ix1 = fmaxf(px1, bx1);
            float iy1 = fmaxf(py1, by1);
            float ix2 = fminf(px2, bx2);
            float iy2 = fminf(py2, by2);
            float si  = fmaxf(ix2 - ix1, 0.0f) * fmaxf(iy2 - iy1, 0.0f);
            float su  = sp + sb - si;
            float iou = (su <= 0.0f || sp <= 0.0f || sb <= 0.0f)
                        ? 0.0f : fmaxf(si / (su + 1e-8f), 0.0f);
            out[OFF_IOU + ((size_t)b * AHW + j) * 64 + n] = iou;
        }
        return;
    }

    // ---- flag-gated transpose + bf16 split ----
    {
        __shared__ float tile[32][33];
        __shared__ unsigned char sflag[32];
        int r  = bid - (W1_BLKS + IOU_BLKS);
        int pt = r % 25;
        int kt = (r / 25) % 40;
        int b  = r / 1000;
        const int p0 = pt * 32;
        const int k0 = kt * 32;
        const int tx = t & 31;
        const int ty = t >> 5;    // 0..7

        const int p = p0 + tx;
#pragma unroll
        for (int jj = 0; jj < 4; jj++) {
            int kk = ty + jj * 8;
            tile[kk][tx] = (p < HW)
                ? feat[((size_t)b * CIN + (k0 + kk)) * HW + p] : 0.0f;
        }
        if (t < 32) {
            int pp = p0 + t;
            sflag[t] = (pp < HW) ? g_flag[b * HW + pp] : 0;
        }
        __syncthreads();

        const int k = k0 + tx;
#pragma unroll
        for (int jj = 0; jj < 4; jj++) {
            int pi = ty + jj * 8;
            int pp = p0 + pi;
            if (pp < HW && sflag[pi]) {
                float v = tile[tx][pi];
                __nv_bfloat16 h = __float2bfloat16(v);
                size_t o = (size_t)(b * HW + pp) * CIN + k;
                g_fT_hi[o] = h;
                g_fT_lo[o] = __float2bfloat16(v - __bfloat162float(h));
            }
        }
    }
}

// ---------------------------------------------------------------------------
// Kernel 2: gathered WMMA GEMM with cp.async double-buffered pipeline.
//   Block: 64 gathered rows x 128 cols, 8 warps (4x2), K-chunks of 64.
//   3-term bf16 split, fp32 accum.
// ---------------------------------------------------------------------------
#define LDA 72
#define LDB 72
#define NCHUNK 20
// per-stage element offsets (bf16 units)
#define SA_HI 0
#define SA_LO (64 * LDA)                      // 4608
#define SB_HI (2 * 64 * LDA)                  // 9216
#define SB_LO (2 * 64 * LDA + 128 * LDB)      // 18432
#define STAGE_ELEMS (2 * 64 * LDA + 2 * 128 * LDB)   // 27648
#define SMEM_GEMM_BYTES (2 * STAGE_ELEMS * 2)        // 110592
#define LDS_STAGE 132

extern __shared__ __nv_bfloat16 smem_g[];

__device__ __forceinline__ void gemm_issue(uint32_t sbase, int k0,
                                           const int* __restrict__ srow, int t) {
#pragma unroll
    for (int h = 0; h < 2; h++) {
        int q = t + h * 256;
        int row = q >> 3;
        int j   = q & 7;
        size_t src = (size_t)srow[row] * CIN + k0 + j * 8;
        cpa16(sbase + (SA_HI + row * LDA + j * 8) * 2, g_fT_hi + src);
        cpa16(sbase + (SA_LO + row * LDA + j * 8) * 2, g_fT_lo + src);
    }
#pragma unroll
    for (int h = 0; h < 4; h++) {
        int q = t + h * 256;
        int n = q >> 3;
        int j = q & 7;
        size_t src = (size_t)n * CIN + k0 + j * 8;
        cpa16(sbase + (SB_HI + n * LDB + j * 8) * 2, g_W1hi + src);
        cpa16(sbase + (SB_LO + n * LDB + j * 8) * 2, g_W1lo + src);
    }
}

__global__ void __launch_bounds__(256, 1)
gemm_wmma_kernel(const int* __restrict__ pos,
                 const int* __restrict__ neg,
                 const float* __restrict__ b1) {
    __shared__ int srow[64];

    const int t   = threadIdx.x;
    const int wid = t >> 5;
    const int i0  = blockIdx.x * 64;

    if (t < 64) {
        int gi  = i0 + t;
        int idx = (gi < M_) ? pos[gi] : neg[gi - M_];
        int p   = idx % HW;
        int b   = idx / (HW * A_);
        srow[t] = b * HW + p;
    }
    __syncthreads();

    const uint32_t sb0 = smem_u32(smem_g);
    const uint32_t sb1 = sb0 + STAGE_ELEMS * 2;

    const int wr = wid >> 1;     // 0..3 -> rows wr*16
    const int wc = wid & 1;      // 0..1 -> cols wc*64

    wmma::fragment<wmma::accumulator, 16, 16, 16, float> acc[4];
#pragma unroll
    for (int nt = 0; nt < 4; nt++) wmma::fill_fragment(acc[nt], 0.0f);

    // prologue
    gemm_issue(sb0, 0, srow, t);
    CP_COMMIT();

    for (int c = 0; c < NCHUNK; c++) {
        if (c + 1 < NCHUNK) {
            gemm_issue((c + 1) & 1 ? sb1 : sb0, (c + 1) * 64, srow, t);
            CP_COMMIT();
            CP_WAIT1();
        } else {
            CP_WAIT0();
        }
        __syncthreads();

        const __nv_bfloat16* buf = smem_g + (c & 1) * STAGE_ELEMS;
#pragma unroll
        for (int ks = 0; ks < 4; ks++) {
            wmma::fragment<wmma::matrix_a, 16, 16, 16, __nv_bfloat16, wmma::row_major> a_hi, a_lo;
            wmma::load_matrix_sync(a_hi, buf + SA_HI + (wr * 16) * LDA + ks * 16, LDA);
            wmma::load_matrix_sync(a_lo, buf + SA_LO + (wr * 16) * LDA + ks * 16, LDA);
#pragma unroll
            for (int nt = 0; nt < 4; nt++) {
                int n = wc * 64 + nt * 16;
                wmma::fragment<wmma::matrix_b, 16, 16, 16, __nv_bfloat16, wmma::col_major> b_hi, b_lo;
                wmma::load_matrix_sync(b_hi, buf + SB_HI + n * LDB + ks * 16, LDB);
                wmma::load_matrix_sync(b_lo, buf + SB_LO + n * LDB + ks * 16, LDB);
                wmma::mma_sync(acc[nt], a_hi, b_hi, acc[nt]);
                wmma::mma_sync(acc[nt], a_hi, b_lo, acc[nt]);
                wmma::mma_sync(acc[nt], a_lo, b_hi, acc[nt]);
            }
        }
        __syncthreads();
    }

    // epilogue: stage in smem, bias + leaky, store
    float* stage = (float*)smem_g;
#pragma unroll
    for (int nt = 0; nt < 4; nt++) {
        wmma::store_matrix_sync(&stage[(wr * 16) * LDS_STAGE + wc * 64 + nt * 16],
                                acc[nt], LDS_STAGE, wmma::mem_row_major);
    }
    __syncthreads();

    for (int i = t; i < 64 * 32; i += 256) {
        int row = i >> 5;
        int c4  = (i & 31) * 4;
        float4 v = *(float4*)&stage[row * LDS_STAGE + c4];
        v.x += b1[c4 + 0]; v.y += b1[c4 + 1]; v.z += b1[c4 + 2]; v.w += b1[c4 + 3];
        v.x = (v.x > 0.f) ? v.x : 0.01f * v.x;
        v.y = (v.y > 0.f) ? v.y : 0.01f * v.y;
        v.z = (v.z > 0.f) ? v.z : 0.01f * v.z;
        v.w = (v.w > 0.f) ? v.w : 0.01f * v.w;
        *(float4*)&g_H[(size_t)(i0 + row) * HID + c4] = v;
    }
}

// ---------------------------------------------------------------------------
// Kernel 3: head (unchanged)
// ---------------------------------------------------------------------------
__device__ __forceinline__ float sigmoidf_(float x) {
    return 1.0f / (1.0f + expf(-x));
}

__global__ void head_kernel(const float* __restrict__ W2,
                            const float* __restrict__ b2,
                            const int* __restrict__ pos,
                            const int* __restrict__ neg,
                            float* __restrict__ out) {
    int gw   = (blockIdx.x * blockDim.x + threadIdx.x) >> 5;
    int lane = threadIdx.x & 31;
    if (gw >= MTOT) return;

    float4 hv = ((const float4*)(g_H + (size_t)gw * HID))[lane];

    int idx = (gw < M_) ? pos[gw] : neg[gw - M_];
    int a   = (idx / HW) % A_;

    if (gw < M_) {
#pragma unroll
        for (int r = 0; r < 25; r++) {
            int row = (r < 5) ? (a * 5 + r) : (40 + r);
            float4 wv = ((const float4*)(W2 + row * HID))[lane];
            float s = wv.x * hv.x + wv.y * hv.y + wv.z * hv.z + wv.w * hv.w;
#pragma unroll
            for (int o = 16; o; o >>= 1) s += __shfl_xor_sync(0xffffffffu, s, o);
            if (lane == 0) {
                s += b2[row];
                if (r == 0) {
                    out[OFF_CONF + gw] = sigmoidf_(s);
                } else if (r <= 2) {
                    out[OFF_OFFS + gw * 4 + (r - 1)] = sigmoidf_(s) - 0.5f;
                } else if (r <= 4) {
                    out[OFF_OFFS + gw * 4 + (r - 1)] = s;
                } else {
                    out[OFF_CLASS + gw * 20 + (r - 5)] = s;
                }
            }
        }
    } else {
        int row = a * 5;
        float4 wv = ((const float4*)(W2 + row * HID))[lane];
        float s = wv.x * hv.x + wv.y * hv.y + wv.z * hv.z + wv.w * hv.w;
#pragma unroll
        for (int o = 16; o; o >>= 1) s += __shfl_xor_sync(0xffffffffu, s, o);
        if (lane == 0) {
            out[OFF_CONF + gw] = sigmoidf_(s + b2[row]);
        }
    }
}

// ---------------------------------------------------------------------------
// Launch
// ---------------------------------------------------------------------------
extern "C" void kernel_launch(void* const* d_in, const int* in_sizes, int n_in,
                              void* d_out, int out_size) {
    const float* features = (const float*)d_in[0];
    const float* grid     = (const float*)d_in[1];
    const float* anc      = (const float*)d_in[2];
    const float* bboxes   = (const float*)d_in[3];
    const int*   pos      = (const int*)d_in[4];
    const int*   neg      = (const int*)d_in[5];
    const float* W1       = (const float*)d_in[6];
    const float* b1       = (const float*)d_in[7];
    const float* W2       = (const float*)d_in[8];
    const float* b2       = (const float*)d_in[9];
    float* out = (float*)d_out;

    // mark gathered rows (idempotent, deterministic)
    mark_kernel<<<MTOT / 256, 256>>>(pos, neg);

    // fused prep: w1 split + IoU + flag-gated transpose/split
    prep_kernel<<<PREP_BLKS, 256>>>(features, W1, grid, anc, bboxes, out);

    // gathered WMMA GEMM (cp.async pipelined)
    cudaFuncSetAttribute(gemm_wmma_kernel,
                         cudaFuncAttributeMaxDynamicSharedMemorySize,
                         SMEM_GEMM_BYTES);
    gemm_wmma_kernel<<<MTOT / 64, 256, SMEM_GEMM_BYTES>>>(pos, neg, b1);

    // head
    head_kernel<<<MTOT / 8, 256>>>(W2, b2, pos, neg, out);
}

// round 6
// speedup vs baseline: 1.7968x; 1.0109x over previous
#include <cuda_runtime.h>
#include <cuda_bf16.h>
#include <mma.h>
#include <math.h>
#include <stdint.h>

using namespace nvcuda;

// ---------------- problem constants ----------------
#define B_    32
#define CIN   1280
#define HH    28
#define WW    28
#define HW    784
#define A_    9
#define HID   128
#define M_    4096
#define MTOT  8192
#define AHW   7056
#define NPOS  (B_ * HW)        // 25088

// output layout
#define OFF_CONF   0
#define OFF_OFFS   8192
#define OFF_CLASS  24576
#define OFF_IOU    106496

// ---------------- scratch (__device__ globals; no cudaMalloc) ----------------
__device__ __nv_bfloat16 g_fT_hi[(size_t)NPOS * CIN];   // [b*HW+p][k]
__device__ __nv_bfloat16 g_fT_lo[(size_t)NPOS * CIN];
__device__ __nv_bfloat16 g_W1hi[HID * CIN];             // [n][k]
__device__ __nv_bfloat16 g_W1lo[HID * CIN];
__device__ float g_H[MTOT * HID];
__device__ unsigned char g_flag[NPOS];                  // zero-init; marking idempotent

// ---------------- helpers ----------------
__device__ __forceinline__ uint32_t smem_u32(const void* p) {
    uint32_t a;
    asm("{ .reg .u64 t; cvta.to.shared.u64 t, %1; cvt.u32.u64 %0, t; }"
        : "=r"(a) : "l"(p));
    return a;
}
__device__ __forceinline__ uint32_t PK(__nv_bfloat16 a, __nv_bfloat16 b) {
    unsigned short ua = *(unsigned short*)&a;
    unsigned short ub = *(unsigned short*)&b;
    return (uint32_t)ua | ((uint32_t)ub << 16);
}
__device__ __forceinline__ void cpa16(uint32_t dst, const void* src) {
    asm volatile("cp.async.ca.shared.global [%0], [%1], 16;" :: "r"(dst), "l"(src));
}
#define CP_COMMIT() asm volatile("cp.async.commit_group;" ::: "memory")
#define CP_WAIT0()  asm volatile("cp.async.wait_group 0;" ::: "memory")
#define CP_WAIT1()  asm volatile("cp.async.wait_group 1;" ::: "memory")

// ---------------------------------------------------------------------------
// Kernel 0: mark gathered rows (idempotent across replays; g_flag zero-init)
// ---------------------------------------------------------------------------
__global__ void mark_kernel(const int* __restrict__ pos,
                            const int* __restrict__ neg) {
    int i = blockIdx.x * blockDim.x + threadIdx.x;
    if (i >= MTOT) return;
    int idx = (i < M_) ? pos[i] : neg[i - M_];
    int p = idx % HW;
    int b = idx / (HW * A_);
    g_flag[b * HW + p] = 1;
}

// ---------------------------------------------------------------------------
// Kernel 1: fused prep = w1 split  +  IoU  +  flag-gated transpose/split
// ---------------------------------------------------------------------------
#define W1_BLKS  160
#define IOU_BLKS (56 * 32)
#define TR_BLKS  (25 * 40 * 32)
#define PREP_BLKS (W1_BLKS + IOU_BLKS + TR_BLKS)

__global__ void __launch_bounds__(256)
prep_kernel(const float* __restrict__ feat,
            const float* __restrict__ W1,
            const float* __restrict__ grid,
            const float* __restrict__ anc,
            const float* __restrict__ bboxes,
            float* __restrict__ out) {
    const int bid = blockIdx.x;
    const int t   = threadIdx.x;

    if (bid < W1_BLKS) {
        int i4 = bid * 256 + t;
        const float4 v = ((const float4*)W1)[i4];
        __nv_bfloat16 h0 = __float2bfloat16(v.x), h1 = __float2bfloat16(v.y);
        __nv_bfloat16 h2 = __float2bfloat16(v.z), h3 = __float2bfloat16(v.w);
        ((uint2*)g_W1hi)[i4] = make_uint2(PK(h0, h1), PK(h2, h3));
        ((uint2*)g_W1lo)[i4] = make_uint2(
            PK(__float2bfloat16(v.x - __bfloat162float(h0)),
               __float2bfloat16(v.y - __bfloat162float(h1))),
            PK(__float2bfloat16(v.z - __bfloat162float(h2)),
               __float2bfloat16(v.w - __bfloat162float(h3))));
        return;
    }

    if (bid < W1_BLKS + IOU_BLKS) {
        __shared__ float s_x1[64], s_y1[64], s_x2[64], s_y2[64], s_sb[64];
        int r  = bid - W1_BLKS;
        int bx = r % 56;
        int b  = r / 56;

        if (t < 64) {
            const float* bb = bboxes + ((size_t)b * 64 + t) * 5;
            float x1 = bb[0], y1 = bb[1], x2 = bb[2], y2 = bb[3];
            s_x1[t] = x1; s_y1[t] = y1; s_x2[t] = x2; s_y2[t] = y2;
            float sb = (x2 - x1) * (y2 - y1);
            s_sb[t] = (x1 < 0.0f) ? 0.0f : sb;
        }
        __syncthreads();

        const int n  = t & 63;
        const int jl = t >> 6;
        const int j0 = bx * 128;
        const float bx1 = s_x1[n], by1 = s_y1[n], bx2 = s_x2[n], by2 = s_y2[n];
        const float sb  = s_sb[n];

        for (int jj = jl; jj < 128; jj += 4) {
            int j = j0 + jj;
            if (j >= AHW) break;
            int a = j / HW;
            int rr = j - a * HW;
            int h = rr / WW;
            int w = rr - h * WW;
            float cx = grid[(((size_t)b * HH + h) * WW + w) * 2 + 0];
            float cy = grid[(((size_t)b * HH + h) * WW + w) * 2 + 1];
            float hw2 = anc[a * 2 + 0] * 0.5f;
            float hh2 = anc[a * 2 + 1] * 0.5f;
            float px1 = cx - hw2, py1 = cy - hh2, px2 = cx + hw2, py2 = cy + hh2;
            float sp  = (px2 - px1) * (py2 - py1);
            float ix1 = fmaxf(px1, bx1);
            float iy1 = fmaxf(py1, by1);
            float ix2 = fminf(px2, bx2);
            float iy2 = fminf(py2, by2);
            float si  = fmaxf(ix2 - ix1, 0.0f) * fmaxf(iy2 - iy1, 0.0f);
            float su  = sp + sb - si;
            float iou = (su <= 0.0f || sp <= 0.0f || sb <= 0.0f)
                        ? 0.0f : fmaxf(si / (su + 1e-8f), 0.0f);
            out[OFF_IOU + ((size_t)b * AHW + j) * 64 + n] = iou;
        }
        return;
    }

    // ---- flag-gated transpose + bf16 split ----
    {
        __shared__ float tile[32][33];
        __shared__ unsigned char sflag[32];
        int r  = bid - (W1_BLKS + IOU_BLKS);
        int pt = r % 25;
        int kt = (r / 25) % 40;
        int b  = r / 1000;
        const int p0 = pt * 32;
        const int k0 = kt * 32;
        const int tx = t & 31;
        const int ty = t >> 5;

        const int p = p0 + tx;
#pragma unroll
        for (int jj = 0; jj < 4; jj++) {
            int kk = ty + jj * 8;
            tile[kk][tx] = (p < HW)
                ? feat[((size_t)b * CIN + (k0 + kk)) * HW + p] : 0.0f;
        }
        if (t < 32) {
            int pp = p0 + t;
            sflag[t] = (pp < HW) ? g_flag[b * HW + pp] : 0;
        }
        __syncthreads();

        const int k = k0 + tx;
#pragma unroll
        for (int jj = 0; jj < 4; jj++) {
            int pi = ty + jj * 8;
            int pp = p0 + pi;
            if (pp < HW && sflag[pi]) {
                float v = tile[tx][pi];
                __nv_bfloat16 h = __float2bfloat16(v);
                size_t o = (size_t)(b * HW + pp) * CIN + k;
                g_fT_hi[o] = h;
                g_fT_lo[o] = __float2bfloat16(v - __bfloat162float(h));
            }
        }
    }
}

// ---------------------------------------------------------------------------
// Kernel 2: gathered WMMA GEMM, 512 threads (16 warps, 4x4), warp tile 16x32.
//   Block: 64 gathered rows x 128 cols, K-chunks of 64, cp.async depth-2.
//   3-term bf16 split, fp32 accum.
// ---------------------------------------------------------------------------
#define LDA 72
#define LDB 72
#define NCHUNK 20
#define SA_HI 0
#define SA_LO (64 * LDA)                      // 4608
#define SB_HI (2 * 64 * LDA)                  // 9216
#define SB_LO (2 * 64 * LDA + 128 * LDB)      // 18432
#define STAGE_ELEMS (2 * 64 * LDA + 2 * 128 * LDB)   // 27648
#define SMEM_GEMM_BYTES (2 * STAGE_ELEMS * 2)        // 110592
#define LDS_STAGE 132

extern __shared__ __nv_bfloat16 smem_g[];

__device__ __forceinline__ void gemm_issue(uint32_t sbase, int k0,
                                           const int* __restrict__ srow, int t) {
    // A tiles: 64 rows x 64 k = 512 uint4 per array; 1 per thread
    {
        int row = t >> 3;
        int j   = t & 7;
        size_t src = (size_t)srow[row] * CIN + k0 + j * 8;
        cpa16(sbase + (SA_HI + row * LDA + j * 8) * 2, g_fT_hi + src);
        cpa16(sbase + (SA_LO + row * LDA + j * 8) * 2, g_fT_lo + src);
    }
    // B tiles: 128 n x 64 k = 1024 uint4 per array; 2 per thread
#pragma unroll
    for (int h = 0; h < 2; h++) {
        int q = t + h * 512;
        int n = q >> 3;
        int j = q & 7;
        size_t src = (size_t)n * CIN + k0 + j * 8;
        cpa16(sbase + (SB_HI + n * LDB + j * 8) * 2, g_W1hi + src);
        cpa16(sbase + (SB_LO + n * LDB + j * 8) * 2, g_W1lo + src);
    }
}

__global__ void __launch_bounds__(512, 1)
gemm_wmma_kernel(const int* __restrict__ pos,
                 const int* __restrict__ neg,
                 const float* __restrict__ b1) {
    __shared__ int srow[64];

    const int t   = threadIdx.x;
    const int wid = t >> 5;
    const int i0  = blockIdx.x * 64;

    if (t < 64) {
        int gi  = i0 + t;
        int idx = (gi < M_) ? pos[gi] : neg[gi - M_];
        int p   = idx % HW;
        int b   = idx / (HW * A_);
        srow[t] = b * HW + p;
    }
    __syncthreads();

    const uint32_t sb0 = smem_u32(smem_g);
    const uint32_t sb1 = sb0 + STAGE_ELEMS * 2;

    const int wr = wid >> 2;     // 0..3 -> rows wr*16
    const int wc = wid & 3;      // 0..3 -> cols wc*32

    wmma::fragment<wmma::accumulator, 16, 16, 16, float> acc[2];
#pragma unroll
    for (int nt = 0; nt < 2; nt++) wmma::fill_fragment(acc[nt], 0.0f);

    gemm_issue(sb0, 0, srow, t);
    CP_COMMIT();

    for (int c = 0; c < NCHUNK; c++) {
        if (c + 1 < NCHUNK) {
            gemm_issue((c + 1) & 1 ? sb1 : sb0, (c + 1) * 64, srow, t);
            CP_COMMIT();
            CP_WAIT1();
        } else {
            CP_WAIT0();
        }
        __syncthreads();

        const __nv_bfloat16* buf = smem_g + (c & 1) * STAGE_ELEMS;
#pragma unroll
        for (int ks = 0; ks < 4; ks++) {
            wmma::fragment<wmma::matrix_a, 16, 16, 16, __nv_bfloat16, wmma::row_major> a_hi, a_lo;
            wmma::load_matrix_sync(a_hi, buf + SA_HI + (wr * 16) * LDA + ks * 16, LDA);
            wmma::load_matrix_sync(a_lo, buf + SA_LO + (wr * 16) * LDA + ks * 16, LDA);
#pragma unroll
            for (int nt = 0; nt < 2; nt++) {
                int n = wc * 32 + nt * 16;
                wmma::fragment<wmma::matrix_b, 16, 16, 16, __nv_bfloat16, wmma::col_major> b_hi, b_lo;
                wmma::load_matrix_sync(b_hi, buf + SB_HI + n * LDB + ks * 16, LDB);
                wmma::load_matrix_sync(b_lo, buf + SB_LO + n * LDB + ks * 16, LDB);
                wmma::mma_sync(acc[nt], a_hi, b_hi, acc[nt]);
                wmma::mma_sync(acc[nt], a_hi, b_lo, acc[nt]);
                wmma::mma_sync(acc[nt], a_lo, b_hi, acc[nt]);
            }
        }
        __syncthreads();
    }

    // epilogue: stage in smem, bias + leaky, store
    float* stage = (float*)smem_g;
#pragma unroll
    for (int nt = 0; nt < 2; nt++) {
        wmma::store_matrix_sync(&stage[(wr * 16) * LDS_STAGE + wc * 32 + nt * 16],
                                acc[nt], LDS_STAGE, wmma::mem_row_major);
    }
    __syncthreads();

    for (int i = t; i < 64 * 32; i += 512) {
        int row = i >> 5;
        int c4  = (i & 31) * 4;
        float4 v = *(float4*)&stage[row * LDS_STAGE + c4];
        v.x += b1[c4 + 0]; v.y += b1[c4 + 1]; v.z += b1[c4 + 2]; v.w += b1[c4 + 3];
        v.x = (v.x > 0.f) ? v.x : 0.01f * v.x;
        v.y = (v.y > 0.f) ? v.y : 0.01f * v.y;
        v.z = (v.z > 0.f) ? v.z : 0.01f * v.z;
        v.w = (v.w > 0.f) ? v.w : 0.01f * v.w;
        *(float4*)&g_H[(size_t)(i0 + row) * HID + c4] = v;
    }
}

// ---------------------------------------------------------------------------
// Kernel 3: head (unchanged)
// ---------------------------------------------------------------------------
__device__ __forceinline__ float sigmoidf_(float x) {
    return 1.0f / (1.0f + expf(-x));
}

__global__ void head_kernel(const float* __restrict__ W2,
                            const float* __restrict__ b2,
                            const int* __restrict__ pos,
                            const int* __restrict__ neg,
                            float* __restrict__ out) {
    int gw   = (blockIdx.x * blockDim.x + threadIdx.x) >> 5;
    int lane = threadIdx.x & 31;
    if (gw >= MTOT) return;

    float4 hv = ((const float4*)(g_H + (size_t)gw * HID))[lane];

    int idx = (gw < M_) ? pos[gw] : neg[gw - M_];
    int a   = (idx / HW) % A_;

    if (gw < M_) {
#pragma unroll
        for (int r = 0; r < 25; r++) {
            int row = (r < 5) ? (a * 5 + r) : (40 + r);
            float4 wv = ((const float4*)(W2 + row * HID))[lane];
            float s = wv.x * hv.x + wv.y * hv.y + wv.z * hv.z + wv.w * hv.w;
#pragma unroll
            for (int o = 16; o; o >>= 1) s += __shfl_xor_sync(0xffffffffu, s, o);
            if (lane == 0) {
                s += b2[row];
                if (r == 0) {
                    out[OFF_CONF + gw] = sigmoidf_(s);
                } else if (r <= 2) {
                    out[OFF_OFFS + gw * 4 + (r - 1)] = sigmoidf_(s) - 0.5f;
                } else if (r <= 4) {
                    out[OFF_OFFS + gw * 4 + (r - 1)] = s;
                } else {
                    out[OFF_CLASS + gw * 20 + (r - 5)] = s;
                }
            }
        }
    } else {
        int row = a * 5;
        float4 wv = ((const float4*)(W2 + row * HID))[lane];
        float s = wv.x * hv.x + wv.y * hv.y + wv.z * hv.z + wv.w * hv.w;
#pragma unroll
        for (int o = 16; o; o >>= 1) s += __shfl_xor_sync(0xffffffffu, s, o);
        if (lane == 0) {
            out[OFF_CONF + gw] = sigmoidf_(s + b2[row]);
        }
    }
}

// ---------------------------------------------------------------------------
// Launch
// ---------------------------------------------------------------------------
extern "C" void kernel_launch(void* const* d_in, const int* in_sizes, int n_in,
                              void* d_out, int out_size) {
    const float* features = (const float*)d_in[0];
    const float* grid     = (const float*)d_in[1];
    const float* anc      = (const float*)d_in[2];
    const float* bboxes   = (const float*)d_in[3];
    const int*   pos      = (const int*)d_in[4];
    const int*   neg      = (const int*)d_in[5];
    const float* W1       = (const float*)d_in[6];
    const float* b1       = (const float*)d_in[7];
    const float* W2       = (const float*)d_in[8];
    const float* b2       = (const float*)d_in[9];
    float* out = (float*)d_out;

    // mark gathered rows (idempotent, deterministic)
    mark_kernel<<<MTOT / 256, 256>>>(pos, neg);

    // fused prep: w1 split + IoU + flag-gated transpose/split
    prep_kernel<<<PREP_BLKS, 256>>>(features, W1, grid, anc, bboxes, out);

    // gathered WMMA GEMM (cp.async pipelined, 16 warps/block)
    cudaFuncSetAttribute(gemm_wmma_kernel,
                         cudaFuncAttributeMaxDynamicSharedMemorySize,
                         SMEM_GEMM_BYTES);
    gemm_wmma_kernel<<<MTOT / 64, 512, SMEM_GEMM_BYTES>>>(pos, neg, b1);

    // head
    head_kernel<<<MTOT / 8, 256>>>(W2, b2, pos, neg, out);
}

// round 7
// speedup vs baseline: 1.9338x; 1.0763x over previous
#include <cuda_runtime.h>
#include <cuda_bf16.h>
#include <mma.h>
#include <math.h>
#include <stdint.h>

using namespace nvcuda;

// ---------------- problem constants ----------------
#define B_    32
#define CIN   1280
#define HH    28
#define WW    28
#define HW    784
#define A_    9
#define HID   128
#define M_    4096
#define MTOT  8192
#define AHW   7056
#define NPOS  (B_ * HW)        // 25088

// output layout
#define OFF_CONF   0
#define OFF_OFFS   8192
#define OFF_CLASS  24576
#define OFF_IOU    106496

// ---------------- scratch ----------------
__device__ __nv_bfloat16 g_fT_hi[(size_t)NPOS * CIN];   // [b*HW+p][k]
__device__ __nv_bfloat16 g_fT_lo[(size_t)NPOS * CIN];
__device__ __nv_bfloat16 g_W1hi[HID * CIN];             // [n][k]
__device__ __nv_bfloat16 g_W1lo[HID * CIN];
__device__ float g_H[MTOT * HID];
__device__ unsigned char g_flag[NPOS];                  // zero-init; marking idempotent

// ---------------- helpers ----------------
__device__ __forceinline__ uint32_t smem_u32(const void* p) {
    uint32_t a;
    asm("{ .reg .u64 t; cvta.to.shared.u64 t, %1; cvt.u32.u64 %0, t; }"
        : "=r"(a) : "l"(p));
    return a;
}
__device__ __forceinline__ uint32_t PK(__nv_bfloat16 a, __nv_bfloat16 b) {
    unsigned short ua = *(unsigned short*)&a;
    unsigned short ub = *(unsigned short*)&b;
    return (uint32_t)ua | ((uint32_t)ub << 16);
}
__device__ __forceinline__ void cpa16(uint32_t dst, const void* src) {
    asm volatile("cp.async.ca.shared.global [%0], [%1], 16;" :: "r"(dst), "l"(src));
}
#define CP_COMMIT() asm volatile("cp.async.commit_group;" ::: "memory")
#define CP_WAIT0()  asm volatile("cp.async.wait_group 0;" ::: "memory")
#define CP_WAIT1()  asm volatile("cp.async.wait_group 1;" ::: "memory")
#define CP_WAIT2()  asm volatile("cp.async.wait_group 2;" ::: "memory")

// ---------------------------------------------------------------------------
// Kernel 0: mark gathered rows
// ---------------------------------------------------------------------------
__global__ void mark_kernel(const int* __restrict__ pos,
                            const int* __restrict__ neg) {
    int i = blockIdx.x * blockDim.x + threadIdx.x;
    if (i >= MTOT) return;
    int idx = (i < M_) ? pos[i] : neg[i - M_];
    int p = idx % HW;
    int b = idx / (HW * A_);
    g_flag[b * HW + p] = 1;
}

// ---------------------------------------------------------------------------
// Kernel 1: fused prep.
//   blocks [0, TR_BLKS): transpose 64k x 32p, flag-gated bf16-split writes
//   blocks [TR_BLKS, +IOU_BLKS): IoU (float4 stores)
//   blocks [.., +W1_BLKS): W1 split
// ---------------------------------------------------------------------------
#define TR_BLKS  (25 * 20 * 32)     // 16000
#define IOU_BLKS (56 * 32)          // 1792
#define W1_BLKS  160
#define PREP_BLKS (TR_BLKS + IOU_BLKS + W1_BLKS)

__global__ void __launch_bounds__(256)
prep_kernel(const float* __restrict__ feat,
            const float* __restrict__ W1,
            const float* __restrict__ grid,
            const float* __restrict__ anc,
            const float* __restrict__ bboxes,
            float* __restrict__ out) {
    const int bid = blockIdx.x;
    const int t   = threadIdx.x;

    if (bid < TR_BLKS) {
        // ---- transpose + bf16 split: tile 64k x 32p ----
        __shared__ float tile[64][33];
        __shared__ unsigned char sflag[32];
        int r  = bid;
        int pt = r % 25;
        int kt = (r / 25) % 20;
        int b  = r / 500;
        const int p0 = pt * 32;
        const int k0 = kt * 64;

        // read: 512 float4 (64 k-rows x 8 float4), 2 per thread
#pragma unroll
        for (int h = 0; h < 2; h++) {
            int q  = t + h * 256;
            int kk = q >> 3;
            int j4 = q & 7;
            int p  = p0 + j4 * 4;
            float4 v;
            if (p + 3 < HW) {
                v = *(const float4*)&feat[((size_t)b * CIN + k0 + kk) * HW + p];
            } else {
                v.x = v.y = v.z = v.w = 0.0f;   // only fully-OOB case for our dims
            }
            tile[kk][j4 * 4 + 0] = v.x;
            tile[kk][j4 * 4 + 1] = v.y;
            tile[kk][j4 * 4 + 2] = v.z;
            tile[kk][j4 * 4 + 3] = v.w;
        }
        if (t < 32) {
            int pp = p0 + t;
            sflag[t] = (pp < HW) ? g_flag[b * HW + pp] : 0;
        }
        __syncthreads();

        // convert + store: thread = (p = t>>3, g = t&7) covering 8 k each
        const int p = t >> 3;
        const int g = t & 7;
        if (sflag[p]) {
            size_t base = (size_t)(b * HW + p0 + p) * CIN + k0 + g * 8;
            uint32_t hiw[4], low[4];
#pragma unroll
            for (int i2 = 0; i2 < 4; i2++) {
                float v0 = tile[g * 8 + i2 * 2 + 0][p];
                float v1 = tile[g * 8 + i2 * 2 + 1][p];
                __nv_bfloat16 h0 = __float2bfloat16(v0);
                __nv_bfloat16 h1 = __float2bfloat16(v1);
                hiw[i2] = PK(h0, h1);
                low[i2] = PK(__float2bfloat16(v0 - __bfloat162float(h0)),
                             __float2bfloat16(v1 - __bfloat162float(h1)));
            }
            *(uint4*)&g_fT_hi[base] = make_uint4(hiw[0], hiw[1], hiw[2], hiw[3]);
            *(uint4*)&g_fT_lo[base] = make_uint4(low[0], low[1], low[2], low[3]);
        }
        return;
    }

    if (bid < TR_BLKS + IOU_BLKS) {
        // ---- IoU: block = 128 j x 64 n; thread computes 4 n per j ----
        __shared__ float s_x1[64], s_y1[64], s_x2[64], s_y2[64], s_sb[64];
        int r  = bid - TR_BLKS;
        int bx = r % 56;
        int b  = r / 56;

        if (t < 64) {
            const float* bb = bboxes + ((size_t)b * 64 + t) * 5;
            float x1 = bb[0], y1 = bb[1], x2 = bb[2], y2 = bb[3];
            s_x1[t] = x1; s_y1[t] = y1; s_x2[t] = x2; s_y2[t] = y2;
            float sb = (x2 - x1) * (y2 - y1);
            s_sb[t] = (x1 < 0.0f) ? 0.0f : sb;
        }
        __syncthreads();

        const int n4   = (t & 15) * 4;
        const int jrow = t >> 4;          // 0..15
        const int j0   = bx * 128;

        float bx1[4], by1[4], bx2[4], by2[4], sb4[4];
#pragma unroll
        for (int i = 0; i < 4; i++) {
            bx1[i] = s_x1[n4 + i]; by1[i] = s_y1[n4 + i];
            bx2[i] = s_x2[n4 + i]; by2[i] = s_y2[n4 + i];
            sb4[i] = s_sb[n4 + i];
        }

#pragma unroll
        for (int it = 0; it < 8; it++) {
            int j = j0 + it * 16 + jrow;
            if (j >= AHW) break;
            int a  = j / HW;
            int rr = j - a * HW;
            int h  = rr / WW;
            int w  = rr - h * WW;
            float cx = grid[(((size_t)b * HH + h) * WW + w) * 2 + 0];
            float cy = grid[(((size_t)b * HH + h) * WW + w) * 2 + 1];
            float hw2 = anc[a * 2 + 0] * 0.5f;
            float hh2 = anc[a * 2 + 1] * 0.5f;
            float px1 = cx - hw2, py1 = cy - hh2, px2 = cx + hw2, py2 = cy + hh2;
            float sp  = (px2 - px1) * (py2 - py1);

            float4 v;
            float* vp = &v.x;
#pragma unroll
            for (int i = 0; i < 4; i++) {
                float ix1 = fmaxf(px1, bx1[i]);
                float iy1 = fmaxf(py1, by1[i]);
                float ix2 = fminf(px2, bx2[i]);
                float iy2 = fminf(py2, by2[i]);
                float si  = fmaxf(ix2 - ix1, 0.0f) * fmaxf(iy2 - iy1, 0.0f);
                float su  = sp + sb4[i] - si;
                vp[i] = (su <= 0.0f || sp <= 0.0f || sb4[i] <= 0.0f)
                        ? 0.0f : fmaxf(si / (su + 1e-8f), 0.0f);
            }
            *(float4*)&out[OFF_IOU + ((size_t)b * AHW + j) * 64 + n4] = v;
        }
        return;
    }

    // ---- W1 bf16 hi/lo split ----
    {
        int i4 = (bid - TR_BLKS - IOU_BLKS) * 256 + t;
        const float4 v = ((const float4*)W1)[i4];
        __nv_bfloat16 h0 = __float2bfloat16(v.x), h1 = __float2bfloat16(v.y);
        __nv_bfloat16 h2 = __float2bfloat16(v.z), h3 = __float2bfloat16(v.w);
        ((uint2*)g_W1hi)[i4] = make_uint2(PK(h0, h1), PK(h2, h3));
        ((uint2*)g_W1lo)[i4] = make_uint2(
            PK(__float2bfloat16(v.x - __bfloat162float(h0)),
               __float2bfloat16(v.y - __bfloat162float(h1))),
            PK(__float2bfloat16(v.z - __bfloat162float(h2)),
               __float2bfloat16(v.w - __bfloat162float(h3))));
    }
}

// ---------------------------------------------------------------------------
// Kernel 2: gathered WMMA GEMM, 512 threads (16 warps), 3-stage cp.async.
// ---------------------------------------------------------------------------
#define LDA 72
#define LDB 72
#define NCHUNK 20
#define SA_HI 0
#define SA_LO (64 * LDA)
#define SB_HI (2 * 64 * LDA)
#define SB_LO (2 * 64 * LDA + 128 * LDB)
#define STAGE_ELEMS (2 * 64 * LDA + 2 * 128 * LDB)   // 27648
#define NSTAGE 3
#define SMEM_GEMM_BYTES (NSTAGE * STAGE_ELEMS * 2)   // 165888
#define LDS_STAGE 132

extern __shared__ __nv_bfloat16 smem_g[];

__device__ __forceinline__ void gemm_issue(uint32_t sbase, int k0,
                                           const int* __restrict__ srow, int t) {
    {
        int row = t >> 3;
        int j   = t & 7;
        size_t src = (size_t)srow[row] * CIN + k0 + j * 8;
        cpa16(sbase + (SA_HI + row * LDA + j * 8) * 2, g_fT_hi + src);
        cpa16(sbase + (SA_LO + row * LDA + j * 8) * 2, g_fT_lo + src);
    }
#pragma unroll
    for (int h = 0; h < 2; h++) {
        int q = t + h * 512;
        int n = q >> 3;
        int j = q & 7;
        size_t src = (size_t)n * CIN + k0 + j * 8;
        cpa16(sbase + (SB_HI + n * LDB + j * 8) * 2, g_W1hi + src);
        cpa16(sbase + (SB_LO + n * LDB + j * 8) * 2, g_W1lo + src);
    }
}

__global__ void __launch_bounds__(512, 1)
gemm_wmma_kernel(const int* __restrict__ pos,
                 const int* __restrict__ neg,
                 const float* __restrict__ b1) {
    __shared__ int srow[64];

    const int t   = threadIdx.x;
    const int wid = t >> 5;
    const int i0  = blockIdx.x * 64;

    if (t < 64) {
        int gi  = i0 + t;
        int idx = (gi < M_) ? pos[gi] : neg[gi - M_];
        int p   = idx % HW;
        int b   = idx / (HW * A_);
        srow[t] = b * HW + p;
    }
    __syncthreads();

    const uint32_t sb = smem_u32(smem_g);

    const int wr = wid >> 2;     // 0..3 -> rows wr*16
    const int wc = wid & 3;      // 0..3 -> cols wc*32

    wmma::fragment<wmma::accumulator, 16, 16, 16, float> acc[2];
#pragma unroll
    for (int nt = 0; nt < 2; nt++) wmma::fill_fragment(acc[nt], 0.0f);

    // prologue: 2 stages in flight
    gemm_issue(sb, 0, srow, t);
    CP_COMMIT();
    gemm_issue(sb + STAGE_ELEMS * 2, 64, srow, t);
    CP_COMMIT();

    int stg = 0;   // stage index of chunk c
    for (int c = 0; c < NCHUNK; c++) {
        if (c + 2 < NCHUNK) {
            int s2 = stg + 2; if (s2 >= NSTAGE) s2 -= NSTAGE;
            gemm_issue(sb + s2 * STAGE_ELEMS * 2, (c + 2) * 64, srow, t);
            CP_COMMIT();
            CP_WAIT2();
        } else if (c + 1 < NCHUNK) {
            CP_WAIT1();
        } else {
            CP_WAIT0();
        }
        __syncthreads();

        const __nv_bfloat16* buf = smem_g + stg * STAGE_ELEMS;
#pragma unroll
        for (int ks = 0; ks < 4; ks++) {
            wmma::fragment<wmma::matrix_a, 16, 16, 16, __nv_bfloat16, wmma::row_major> a_hi, a_lo;
            wmma::load_matrix_sync(a_hi, buf + SA_HI + (wr * 16) * LDA + ks * 16, LDA);
            wmma::load_matrix_sync(a_lo, buf + SA_LO + (wr * 16) * LDA + ks * 16, LDA);
#pragma unroll
            for (int nt = 0; nt < 2; nt++) {
                int n = wc * 32 + nt * 16;
                wmma::fragment<wmma::matrix_b, 16, 16, 16, __nv_bfloat16, wmma::col_major> b_hi, b_lo;
                wmma::load_matrix_sync(b_hi, buf + SB_HI + n * LDB + ks * 16, LDB);
                wmma::load_matrix_sync(b_lo, buf + SB_LO + n * LDB + ks * 16, LDB);
                wmma::mma_sync(acc[nt], a_hi, b_hi, acc[nt]);
                wmma::mma_sync(acc[nt], a_hi, b_lo, acc[nt]);
                wmma::mma_sync(acc[nt], a_lo, b_hi, acc[nt]);
            }
        }
        __syncthreads();
        if (++stg == NSTAGE) stg = 0;
    }

    // epilogue
    float* stage = (float*)smem_g;
#pragma unroll
    for (int nt = 0; nt < 2; nt++) {
        wmma::store_matrix_sync(&stage[(wr * 16) * LDS_STAGE + wc * 32 + nt * 16],
                                acc[nt], LDS_STAGE, wmma::mem_row_major);
    }
    __syncthreads();

    for (int i = t; i < 64 * 32; i += 512) {
        int row = i >> 5;
        int c4  = (i & 31) * 4;
        float4 v = *(float4*)&stage[row * LDS_STAGE + c4];
        v.x += b1[c4 + 0]; v.y += b1[c4 + 1]; v.z += b1[c4 + 2]; v.w += b1[c4 + 3];
        v.x = (v.x > 0.f) ? v.x : 0.01f * v.x;
        v.y = (v.y > 0.f) ? v.y : 0.01f * v.y;
        v.z = (v.z > 0.f) ? v.z : 0.01f * v.z;
        v.w = (v.w > 0.f) ? v.w : 0.01f * v.w;
        *(float4*)&g_H[(size_t)(i0 + row) * HID + c4] = v;
    }
}

// ---------------------------------------------------------------------------
// Kernel 3: head (unchanged)
// ---------------------------------------------------------------------------
__device__ __forceinline__ float sigmoidf_(float x) {
    return 1.0f / (1.0f + expf(-x));
}

__global__ void head_kernel(const float* __restrict__ W2,
                            const float* __restrict__ b2,
                            const int* __restrict__ pos,
                            const int* __restrict__ neg,
                            float* __restrict__ out) {
    int gw   = (blockIdx.x * blockDim.x + threadIdx.x) >> 5;
    int lane = threadIdx.x & 31;
    if (gw >= MTOT) return;

    float4 hv = ((const float4*)(g_H + (size_t)gw * HID))[lane];

    int idx = (gw < M_) ? pos[gw] : neg[gw - M_];
    int a   = (idx / HW) % A_;

    if (gw < M_) {
#pragma unroll
        for (int r = 0; r < 25; r++) {
            int row = (r < 5) ? (a * 5 + r) : (40 + r);
            float4 wv = ((const float4*)(W2 + row * HID))[lane];
            float s = wv.x * hv.x + wv.y * hv.y + wv.z * hv.z + wv.w * hv.w;
#pragma unroll
            for (int o = 16; o; o >>= 1) s += __shfl_xor_sync(0xffffffffu, s, o);
            if (lane == 0) {
                s += b2[row];
                if (r == 0) {
                    out[OFF_CONF + gw] = sigmoidf_(s);
                } else if (r <= 2) {
                    out[OFF_OFFS + gw * 4 + (r - 1)] = sigmoidf_(s) - 0.5f;
                } else if (r <= 4) {
                    out[OFF_OFFS + gw * 4 + (r - 1)] = s;
                } else {
                    out[OFF_CLASS + gw * 20 + (r - 5)] = s;
                }
            }
        }
    } else {
        int row = a * 5;
        float4 wv = ((const float4*)(W2 + row * HID))[lane];
        float s = wv.x * hv.x + wv.y * hv.y + wv.z * hv.z + wv.w * hv.w;
#pragma unroll
        for (int o = 16; o; o >>= 1) s += __shfl_xor_sync(0xffffffffu, s, o);
        if (lane == 0) {
            out[OFF_CONF + gw] = sigmoidf_(s + b2[row]);
        }
    }
}

// ---------------------------------------------------------------------------
// Launch
// ---------------------------------------------------------------------------
extern "C" void kernel_launch(void* const* d_in, const int* in_sizes, int n_in,
                              void* d_out, int out_size) {
    const float* features = (const float*)d_in[0];
    const float* grid     = (const float*)d_in[1];
    const float* anc      = (const float*)d_in[2];
    const float* bboxes   = (const float*)d_in[3];
    const int*   pos      = (const int*)d_in[4];
    const int*   neg      = (const int*)d_in[5];
    const float* W1       = (const float*)d_in[6];
    const float* b1       = (const float*)d_in[7];
    const float* W2       = (const float*)d_in[8];
    const float* b2       = (const float*)d_in[9];
    float* out = (float*)d_out;

    mark_kernel<<<MTOT / 256, 256>>>(pos, neg);

    prep_kernel<<<PREP_BLKS, 256>>>(features, W1, grid, anc, bboxes, out);

    cudaFuncSetAttribute(gemm_wmma_kernel,
                         cudaFuncAttributeMaxDynamicSharedMemorySize,
                         SMEM_GEMM_BYTES);
    gemm_wmma_kernel<<<MTOT / 64, 512, SMEM_GEMM_BYTES>>>(pos, neg, b1);

    head_kernel<<<MTOT / 8, 256>>>(W2, b2, pos, neg, out);
}

// round 8
// speedup vs baseline: 2.0666x; 1.0687x over previous
#include <cuda_runtime.h>
#include <cuda_bf16.h>
#include <mma.h>
#include <math.h>
#include <stdint.h>

using namespace nvcuda;

// ---------------- problem constants ----------------
#define B_    32
#define CIN   1280
#define HH    28
#define WW    28
#define HW    784
#define A_    9
#define HID   128
#define M_    4096
#define MTOT  8192
#define AHW   7056
#define NPOS  (B_ * HW)        // 25088

// output layout
#define OFF_CONF   0
#define OFF_OFFS   8192
#define OFF_CLASS  24576
#define OFF_IOU    106496

// ---------------- scratch ----------------
__device__ __nv_bfloat16 g_fT_hi[(size_t)NPOS * CIN];   // [b*HW+p][k]
__device__ __nv_bfloat16 g_fT_lo[(size_t)NPOS * CIN];
__device__ __nv_bfloat16 g_W1hi[HID * CIN];             // [n][k]
__device__ __nv_bfloat16 g_W1lo[HID * CIN];
__device__ __nv_bfloat16 g_W2hi[80 * HID];              // rows 65..79 stay zero
__device__ __nv_bfloat16 g_W2lo[80 * HID];
__device__ unsigned char g_flag[NPOS];                  // zero-init; marking idempotent

// ---------------- helpers ----------------
__device__ __forceinline__ uint32_t smem_u32(const void* p) {
    uint32_t a;
    asm("{ .reg .u64 t; cvta.to.shared.u64 t, %1; cvt.u32.u64 %0, t; }"
        : "=r"(a) : "l"(p));
    return a;
}
__device__ __forceinline__ uint32_t PK(__nv_bfloat16 a, __nv_bfloat16 b) {
    unsigned short ua = *(unsigned short*)&a;
    unsigned short ub = *(unsigned short*)&b;
    return (uint32_t)ua | ((uint32_t)ub << 16);
}
__device__ __forceinline__ void cpa16(uint32_t dst, const void* src) {
    asm volatile("cp.async.ca.shared.global [%0], [%1], 16;" :: "r"(dst), "l"(src));
}
#define CP_COMMIT() asm volatile("cp.async.commit_group;" ::: "memory")
#define CP_WAIT0()  asm volatile("cp.async.wait_group 0;" ::: "memory")
#define CP_WAIT1()  asm volatile("cp.async.wait_group 1;" ::: "memory")
#define CP_WAIT2()  asm volatile("cp.async.wait_group 2;" ::: "memory")

__device__ __forceinline__ float sigmoidf_(float x) {
    return 1.0f / (1.0f + expf(-x));
}

// ---------------------------------------------------------------------------
// Kernel 0: mark gathered rows
// ---------------------------------------------------------------------------
__global__ void mark_kernel(const int* __restrict__ pos,
                            const int* __restrict__ neg) {
    int i = blockIdx.x * blockDim.x + threadIdx.x;
    if (i >= MTOT) return;
    int idx = (i < M_) ? pos[i] : neg[i - M_];
    int p = idx % HW;
    int b = idx / (HW * A_);
    g_flag[b * HW + p] = 1;
}

// ---------------------------------------------------------------------------
// Kernel 1: fused prep.
//   [0, TR_BLKS): transpose: one block per (b, p-tile), loops 20 k-tiles
//   [TR_BLKS, +IOU_BLKS): IoU (float4 stores)
//   [.., +W1_BLKS): W1 split
//   [.., +W2_BLKS): W2 split
// ---------------------------------------------------------------------------
#define TR_BLKS  (25 * 32)          // 800
#define IOU_BLKS (56 * 32)          // 1792
#define W1_BLKS  160
#define W2_BLKS  9                  // ceil(65*128/4 / 256) = 9
#define PREP_BLKS (TR_BLKS + IOU_BLKS + W1_BLKS + W2_BLKS)

__global__ void __launch_bounds__(256)
prep_kernel(const float* __restrict__ feat,
            const float* __restrict__ W1,
            const float* __restrict__ W2,
            const float* __restrict__ grid,
            const float* __restrict__ anc,
            const float* __restrict__ bboxes,
            float* __restrict__ out) {
    const int bid = blockIdx.x;
    const int t   = threadIdx.x;

    if (bid < TR_BLKS) {
        // ---- transpose + bf16 split: (b, p-tile), loop 20 k-tiles of 64 ----
        __shared__ float tile[64][33];
        __shared__ unsigned char sflag[32];
        int pt = bid % 25;
        int b  = bid / 25;
        const int p0 = pt * 32;
        if (t < 32) {
            int pp = p0 + t;
            sflag[t] = (pp < HW) ? g_flag[b * HW + pp] : 0;
        }

        const int pr = t >> 3;        // store-phase p (0..31)
        const int gq = t & 7;         // store-phase k-group (0..7)

        for (int kt = 0; kt < 20; kt++) {
            const int k0 = kt * 64;
            __syncthreads();
#pragma unroll
            for (int h = 0; h < 2; h++) {
                int q  = t + h * 256;
                int kk = q >> 3;
                int j4 = q & 7;
                int p  = p0 + j4 * 4;
                float4 v = make_float4(0.f, 0.f, 0.f, 0.f);
                if (p + 3 < HW)
                    v = *(const float4*)&feat[((size_t)b * CIN + k0 + kk) * HW + p];
                tile[kk][j4 * 4 + 0] = v.x;
                tile[kk][j4 * 4 + 1] = v.y;
                tile[kk][j4 * 4 + 2] = v.z;
                tile[kk][j4 * 4 + 3] = v.w;
            }
            __syncthreads();

            if (sflag[pr]) {
                size_t base = (size_t)(b * HW + p0 + pr) * CIN + k0 + gq * 8;
                uint32_t hiw[4], low[4];
#pragma unroll
                for (int i2 = 0; i2 < 4; i2++) {
                    float v0 = tile[gq * 8 + i2 * 2 + 0][pr];
                    float v1 = tile[gq * 8 + i2 * 2 + 1][pr];
                    __nv_bfloat16 h0 = __float2bfloat16(v0);
                    __nv_bfloat16 h1 = __float2bfloat16(v1);
                    hiw[i2] = PK(h0, h1);
                    low[i2] = PK(__float2bfloat16(v0 - __bfloat162float(h0)),
                                 __float2bfloat16(v1 - __bfloat162float(h1)));
                }
                *(uint4*)&g_fT_hi[base] = make_uint4(hiw[0], hiw[1], hiw[2], hiw[3]);
                *(uint4*)&g_fT_lo[base] = make_uint4(low[0], low[1], low[2], low[3]);
            }
        }
        return;
    }

    if (bid < TR_BLKS + IOU_BLKS) {
        // ---- IoU: block = 128 j x 64 n; thread computes 4 n per j ----
        __shared__ float s_x1[64], s_y1[64], s_x2[64], s_y2[64], s_sb[64];
        int r  = bid - TR_BLKS;
        int bx = r % 56;
        int b  = r / 56;

        if (t < 64) {
            const float* bb = bboxes + ((size_t)b * 64 + t) * 5;
            float x1 = bb[0], y1 = bb[1], x2 = bb[2], y2 = bb[3];
            s_x1[t] = x1; s_y1[t] = y1; s_x2[t] = x2; s_y2[t] = y2;
            float sb = (x2 - x1) * (y2 - y1);
            s_sb[t] = (x1 < 0.0f) ? 0.0f : sb;
        }
        __syncthreads();

        const int n4   = (t & 15) * 4;
        const int jrow = t >> 4;          // 0..15
        const int j0   = bx * 128;

        float bx1[4], by1[4], bx2[4], by2[4], sb4[4];
#pragma unroll
        for (int i = 0; i < 4; i++) {
            bx1[i] = s_x1[n4 + i]; by1[i] = s_y1[n4 + i];
            bx2[i] = s_x2[n4 + i]; by2[i] = s_y2[n4 + i];
            sb4[i] = s_sb[n4 + i];
        }

#pragma unroll
        for (int it = 0; it < 8; it++) {
            int j = j0 + it * 16 + jrow;
            if (j >= AHW) break;
            int a  = j / HW;
            int rr = j - a * HW;
            int h  = rr / WW;
            int w  = rr - h * WW;
            float cx = grid[(((size_t)b * HH + h) * WW + w) * 2 + 0];
            float cy = grid[(((size_t)b * HH + h) * WW + w) * 2 + 1];
            float hw2 = anc[a * 2 + 0] * 0.5f;
            float hh2 = anc[a * 2 + 1] * 0.5f;
            float px1 = cx - hw2, py1 = cy - hh2, px2 = cx + hw2, py2 = cy + hh2;
            float sp  = (px2 - px1) * (py2 - py1);

            float4 v;
            float* vp = &v.x;
#pragma unroll
            for (int i = 0; i < 4; i++) {
                float ix1 = fmaxf(px1, bx1[i]);
                float iy1 = fmaxf(py1, by1[i]);
                float ix2 = fminf(px2, bx2[i]);
                float iy2 = fminf(py2, by2[i]);
                float si  = fmaxf(ix2 - ix1, 0.0f) * fmaxf(iy2 - iy1, 0.0f);
                float su  = sp + sb4[i] - si;
                vp[i] = (su <= 0.0f || sp <= 0.0f || sb4[i] <= 0.0f)
                        ? 0.0f : fmaxf(si / (su + 1e-8f), 0.0f);
            }
            *(float4*)&out[OFF_IOU + ((size_t)b * AHW + j) * 64 + n4] = v;
        }
        return;
    }

    if (bid < TR_BLKS + IOU_BLKS + W1_BLKS) {
        // ---- W1 bf16 hi/lo split ----
        int i4 = (bid - TR_BLKS - IOU_BLKS) * 256 + t;
        const float4 v = ((const float4*)W1)[i4];
        __nv_bfloat16 h0 = __float2bfloat16(v.x), h1 = __float2bfloat16(v.y);
        __nv_bfloat16 h2 = __float2bfloat16(v.z), h3 = __float2bfloat16(v.w);
        ((uint2*)g_W1hi)[i4] = make_uint2(PK(h0, h1), PK(h2, h3));
        ((uint2*)g_W1lo)[i4] = make_uint2(
            PK(__float2bfloat16(v.x - __bfloat162float(h0)),
               __float2bfloat16(v.y - __bfloat162float(h1))),
            PK(__float2bfloat16(v.z - __bfloat162float(h2)),
               __float2bfloat16(v.w - __bfloat162float(h3))));
        return;
    }

    // ---- W2 bf16 hi/lo split (65*128 floats = 2080 float4) ----
    {
        int i4 = (bid - TR_BLKS - IOU_BLKS - W1_BLKS) * 256 + t;
        if (i4 < (65 * HID) / 4) {
            const float4 v = ((const float4*)W2)[i4];
            __nv_bfloat16 h0 = __float2bfloat16(v.x), h1 = __float2bfloat16(v.y);
            __nv_bfloat16 h2 = __float2bfloat16(v.z), h3 = __float2bfloat16(v.w);
            ((uint2*)g_W2hi)[i4] = make_uint2(PK(h0, h1), PK(h2, h3));
            ((uint2*)g_W2lo)[i4] = make_uint2(
                PK(__float2bfloat16(v.x - __bfloat162float(h0)),
                   __float2bfloat16(v.y - __bfloat162float(h1))),
                PK(__float2bfloat16(v.z - __bfloat162float(h2)),
                   __float2bfloat16(v.w - __bfloat162float(h3))));
        }
    }
}

// ---------------------------------------------------------------------------
// Kernel 2: gathered WMMA GEMM + fused head epilogue.
//   Main: 64 rows x 128 cols, K=1280, 3-stage cp.async, 3-term bf16.
//   Epilogue: H (64x128) @ W2^T (padded 80) -> conf/offs/class directly.
// ---------------------------------------------------------------------------
#define LDA 72
#define LDB 72
#define NCHUNK 20
#define SA_HI 0
#define SA_LO (64 * LDA)
#define SB_HI (2 * 64 * LDA)
#define SB_LO (2 * 64 * LDA + 128 * LDB)
#define STAGE_ELEMS (2 * 64 * LDA + 2 * 128 * LDB)   // 27648
#define NSTAGE 3
#define SMEM_GEMM_BYTES (NSTAGE * STAGE_ELEMS * 2)   // 165888

// epilogue smem layout (byte offsets into smem_g)
#define LDS_STAGE 132
#define H_HI_OFF  34816
#define H_LO_OFF  52224
#define LDH       136
#define W2HI_OFF  69632
#define W2LO_OFF  91392
#define LDW2      136
#define ST2_OFF   113152
#define LDS2      84

extern __shared__ __nv_bfloat16 smem_g[];

__device__ __forceinline__ void gemm_issue(uint32_t sbase, int k0,
                                           const int* __restrict__ srow, int t) {
    {
        int row = t >> 3;
        int j   = t & 7;
        size_t src = (size_t)srow[row] * CIN + k0 + j * 8;
        cpa16(sbase + (SA_HI + row * LDA + j * 8) * 2, g_fT_hi + src);
        cpa16(sbase + (SA_LO + row * LDA + j * 8) * 2, g_fT_lo + src);
    }
#pragma unroll
    for (int h = 0; h < 2; h++) {
        int q = t + h * 512;
        int n = q >> 3;
        int j = q & 7;
        size_t src = (size_t)n * CIN + k0 + j * 8;
        cpa16(sbase + (SB_HI + n * LDB + j * 8) * 2, g_W1hi + src);
        cpa16(sbase + (SB_LO + n * LDB + j * 8) * 2, g_W1lo + src);
    }
}

__global__ void __launch_bounds__(512, 1)
gemm_wmma_kernel(const int* __restrict__ pos,
                 const int* __restrict__ neg,
                 const float* __restrict__ b1,
                 const float* __restrict__ b2,
                 float* __restrict__ out) {
    __shared__ int srow[64];
    __shared__ int sanc[64];

    const int t   = threadIdx.x;
    const int wid = t >> 5;
    const int i0  = blockIdx.x * 64;
    const bool isneg = (i0 >= M_);

    if (t < 64) {
        int gi  = i0 + t;
        int idx = (gi < M_) ? pos[gi] : neg[gi - M_];
        int p   = idx % HW;
        int ba  = idx / HW;
        srow[t] = (ba / A_) * HW + p;
        sanc[t] = ba % A_;
    }
    __syncthreads();

    const uint32_t sb = smem_u32(smem_g);

    const int wr = wid >> 2;     // 0..3 -> rows wr*16
    const int wc = wid & 3;      // 0..3 -> cols wc*32

    wmma::fragment<wmma::accumulator, 16, 16, 16, float> acc[2];
#pragma unroll
    for (int nt = 0; nt < 2; nt++) wmma::fill_fragment(acc[nt], 0.0f);

    gemm_issue(sb, 0, srow, t);
    CP_COMMIT();
    gemm_issue(sb + STAGE_ELEMS * 2, 64, srow, t);
    CP_COMMIT();

    int stg = 0;
    for (int c = 0; c < NCHUNK; c++) {
        if (c + 2 < NCHUNK) {
            int s2 = stg + 2; if (s2 >= NSTAGE) s2 -= NSTAGE;
            gemm_issue(sb + s2 * STAGE_ELEMS * 2, (c + 2) * 64, srow, t);
            CP_COMMIT();
            CP_WAIT2();
        } else if (c + 1 < NCHUNK) {
            CP_WAIT1();
        } else {
            CP_WAIT0();
        }
        __syncthreads();

        const __nv_bfloat16* buf = smem_g + stg * STAGE_ELEMS;
#pragma unroll
        for (int ks = 0; ks < 4; ks++) {
            wmma::fragment<wmma::matrix_a, 16, 16, 16, __nv_bfloat16, wmma::row_major> a_hi, a_lo;
            wmma::load_matrix_sync(a_hi, buf + SA_HI + (wr * 16) * LDA + ks * 16, LDA);
            wmma::load_matrix_sync(a_lo, buf + SA_LO + (wr * 16) * LDA + ks * 16, LDA);
#pragma unroll
            for (int nt = 0; nt < 2; nt++) {
                int n = wc * 32 + nt * 16;
                wmma::fragment<wmma::matrix_b, 16, 16, 16, __nv_bfloat16, wmma::col_major> b_hi, b_lo;
                wmma::load_matrix_sync(b_hi, buf + SB_HI + n * LDB + ks * 16, LDB);
                wmma::load_matrix_sync(b_lo, buf + SB_LO + n * LDB + ks * 16, LDB);
                wmma::mma_sync(acc[nt], a_hi, b_hi, acc[nt]);
                wmma::mma_sync(acc[nt], a_hi, b_lo, acc[nt]);
                wmma::mma_sync(acc[nt], a_lo, b_hi, acc[nt]);
            }
        }
        __syncthreads();
        if (++stg == NSTAGE) stg = 0;
    }

    // ---- epilogue 1: accum -> stage (fp32), bias + leaky ----
    float* stage = (float*)smem_g;
#pragma unroll
    for (int nt = 0; nt < 2; nt++) {
        wmma::store_matrix_sync(&stage[(wr * 16) * LDS_STAGE + wc * 32 + nt * 16],
                                acc[nt], LDS_STAGE, wmma::mem_row_major);
    }
    __syncthreads();

    // ---- epilogue 2: h -> bf16 hi/lo in smem; load W2 hi/lo into smem ----
    __nv_bfloat16* hhi  = (__nv_bfloat16*)((char*)smem_g + H_HI_OFF);
    __nv_bfloat16* hlo  = (__nv_bfloat16*)((char*)smem_g + H_LO_OFF);
    __nv_bfloat16* w2hi = (__nv_bfloat16*)((char*)smem_g + W2HI_OFF);
    __nv_bfloat16* w2lo = (__nv_bfloat16*)((char*)smem_g + W2LO_OFF);

    for (int i = t; i < 64 * 32; i += 512) {
        int row = i >> 5;
        int c4  = (i & 31) * 4;
        float4 v = *(float4*)&stage[row * LDS_STAGE + c4];
        v.x += b1[c4 + 0]; v.y += b1[c4 + 1]; v.z += b1[c4 + 2]; v.w += b1[c4 + 3];
        v.x = (v.x > 0.f) ? v.x : 0.01f * v.x;
        v.y = (v.y > 0.f) ? v.y : 0.01f * v.y;
        v.z = (v.z > 0.f) ? v.z : 0.01f * v.z;
        v.w = (v.w > 0.f) ? v.w : 0.01f * v.w;
        __nv_bfloat16 h0 = __float2bfloat16(v.x), h1 = __float2bfloat16(v.y);
        __nv_bfloat16 h2 = __float2bfloat16(v.z), h3 = __float2bfloat16(v.w);
        *(uint2*)&hhi[row * LDH + c4] = make_uint2(PK(h0, h1), PK(h2, h3));
        *(uint2*)&hlo[row * LDH + c4] = make_uint2(
            PK(__float2bfloat16(v.x - __bfloat162float(h0)),
               __float2bfloat16(v.y - __bfloat162float(h1))),
            PK(__float2bfloat16(v.z - __bfloat162float(h2)),
               __float2bfloat16(v.w - __bfloat162float(h3))));
    }
    for (int q = t; q < 80 * 16; q += 512) {
        int n = q >> 4;
        int j = q & 15;
        *(uint4*)&w2hi[n * LDW2 + j * 8] = *(const uint4*)&g_W2hi[n * HID + j * 8];
        *(uint4*)&w2lo[n * LDW2 + j * 8] = *(const uint4*)&g_W2lo[n * HID + j * 8];
    }
    __syncthreads();

    // ---- epilogue 3: D2[64 x 80] = H @ W2^T (3-term bf16) ----
    float* stage2 = (float*)((char*)smem_g + ST2_OFF);
    const int ntile = isneg ? 12 : 20;    // neg needs only cols < 48 (conf rows)
    for (int tid = wid; tid < ntile; tid += 16) {
        int wr2 = tid & 3;
        int wc2 = tid >> 2;
        wmma::fragment<wmma::accumulator, 16, 16, 16, float> acc2;
        wmma::fill_fragment(acc2, 0.0f);
#pragma unroll
        for (int ks = 0; ks < 8; ks++) {
            wmma::fragment<wmma::matrix_a, 16, 16, 16, __nv_bfloat16, wmma::row_major> a_hi, a_lo;
            wmma::load_matrix_sync(a_hi, &hhi[(wr2 * 16) * LDH + ks * 16], LDH);
            wmma::load_matrix_sync(a_lo, &hlo[(wr2 * 16) * LDH + ks * 16], LDH);
            wmma::fragment<wmma::matrix_b, 16, 16, 16, __nv_bfloat16, wmma::col_major> b_hi, b_lo;
            wmma::load_matrix_sync(b_hi, &w2hi[(wc2 * 16) * LDW2 + ks * 16], LDW2);
            wmma::load_matrix_sync(b_lo, &w2lo[(wc2 * 16) * LDW2 + ks * 16], LDW2);
            wmma::mma_sync(acc2, a_hi, b_hi, acc2);
            wmma::mma_sync(acc2, a_hi, b_lo, acc2);
            wmma::mma_sync(acc2, a_lo, b_hi, acc2);
        }
        wmma::store_matrix_sync(&stage2[(wr2 * 16) * LDS2 + wc2 * 16],
                                acc2, LDS2, wmma::mem_row_major);
    }
    __syncthreads();

    // ---- epilogue 4: output mapping ----
    if (!isneg) {
        for (int e = t; e < 64 * 25; e += 512) {
            int row = e / 25;
            int q   = e - row * 25;
            int gi  = i0 + row;
            int a   = sanc[row];
            if (q == 0) {
                int n = 5 * a;
                float s = stage2[row * LDS2 + n] + b2[n];
                out[OFF_CONF + gi] = sigmoidf_(s);
            } else if (q <= 4) {
                int n = 5 * a + q;
                float s = stage2[row * LDS2 + n] + b2[n];
                out[OFF_OFFS + gi * 4 + (q - 1)] = (q <= 2) ? (sigmoidf_(s) - 0.5f) : s;
            } else {
                int n = 40 + q;   // 45 + (q-5)
                float s = stage2[row * LDS2 + n] + b2[n];
                out[OFF_CLASS + gi * 20 + (q - 5)] = s;
            }
        }
    } else {
        if (t < 64) {
            int gi = i0 + t;
            int n  = 5 * sanc[t];
            float s = stage2[t * LDS2 + n] + b2[n];
            out[OFF_CONF + gi] = sigmoidf_(s);
        }
    }
}

// ---------------------------------------------------------------------------
// Launch
// ---------------------------------------------------------------------------
extern "C" void kernel_launch(void* const* d_in, const int* in_sizes, int n_in,
                              void* d_out, int out_size) {
    const float* features = (const float*)d_in[0];
    const float* grid     = (const float*)d_in[1];
    const float* anc      = (const float*)d_in[2];
    const float* bboxes   = (const float*)d_in[3];
    const int*   pos      = (const int*)d_in[4];
    const int*   neg      = (const int*)d_in[5];
    const float* W1       = (const float*)d_in[6];
    const float* b1       = (const float*)d_in[7];
    const float* W2       = (const float*)d_in[8];
    const float* b2       = (const float*)d_in[9];
    float* out = (float*)d_out;

    mark_kernel<<<MTOT / 256, 256>>>(pos, neg);

    prep_kernel<<<PREP_BLKS, 256>>>(features, W1, W2, grid, anc, bboxes, out);

    cudaFuncSetAttribute(gemm_wmma_kernel,
                         cudaFuncAttributeMaxDynamicSharedMemorySize,
                         SMEM_GEMM_BYTES);
    gemm_wmma_kernel<<<MTOT / 64, 512, SMEM_GEMM_BYTES>>>(pos, neg, b1, b2, out);
}

// round 9
// speedup vs baseline: 2.1227x; 1.0271x over previous
#include <cuda_runtime.h>
#include <cuda_bf16.h>
#include <mma.h>
#include <math.h>
#include <stdint.h>

using namespace nvcuda;

// ---------------- problem constants ----------------
#define B_    32
#define CIN   1280
#define HH    28
#define WW    28
#define HW    784
#define A_    9
#define HID   128
#define M_    4096
#define MTOT  8192
#define AHW   7056
#define NPOS  (B_ * HW)        // 25088

// output layout
#define OFF_CONF   0
#define OFF_OFFS   8192
#define OFF_CLASS  24576
#define OFF_IOU    106496

// ---------------- scratch ----------------
__device__ __nv_bfloat16 g_fT_hi[(size_t)NPOS * CIN];   // [b*HW+p][k]
__device__ __nv_bfloat16 g_fT_lo[(size_t)NPOS * CIN];
__device__ __nv_bfloat16 g_W1hi[HID * CIN];             // [n][k]
__device__ __nv_bfloat16 g_W1lo[HID * CIN];
__device__ __nv_bfloat16 g_W2hi[80 * HID];              // rows 65..79 stay zero
__device__ __nv_bfloat16 g_W2lo[80 * HID];

// ---------------- helpers ----------------
__device__ __forceinline__ uint32_t smem_u32(const void* p) {
    uint32_t a;
    asm("{ .reg .u64 t; cvta.to.shared.u64 t, %1; cvt.u32.u64 %0, t; }"
        : "=r"(a) : "l"(p));
    return a;
}
__device__ __forceinline__ uint32_t PK(__nv_bfloat16 a, __nv_bfloat16 b) {
    unsigned short ua = *(unsigned short*)&a;
    unsigned short ub = *(unsigned short*)&b;
    return (uint32_t)ua | ((uint32_t)ub << 16);
}
__device__ __forceinline__ void cpa16(uint32_t dst, const void* src) {
    asm volatile("cp.async.ca.shared.global [%0], [%1], 16;" :: "r"(dst), "l"(src));
}
#define CP_COMMIT() asm volatile("cp.async.commit_group;" ::: "memory")
#define CP_WAIT0()  asm volatile("cp.async.wait_group 0;" ::: "memory")
#define CP_WAIT1()  asm volatile("cp.async.wait_group 1;" ::: "memory")
#define CP_WAIT2()  asm volatile("cp.async.wait_group 2;" ::: "memory")

__device__ __forceinline__ float sigmoidf_(float x) {
    return 1.0f / (1.0f + expf(-x));
}

// ---------------------------------------------------------------------------
// Kernel 1: fused prep.
//   [0, TR_BLKS): transpose (b, p-tile): inline flag scan, cp.async
//                 double-buffered k-tiles, flag-gated bf16-split writes
//   [TR_BLKS, +IOU_BLKS): IoU (float4 stores)
//   [.., +W1_BLKS): W1 split      [.., +W2_BLKS): W2 split
// ---------------------------------------------------------------------------
#define TR_BLKS  (25 * 32)          // 800
#define IOU_BLKS (56 * 32)          // 1792
#define W1_BLKS  160
#define W2_BLKS  9
#define PREP_BLKS (TR_BLKS + IOU_BLKS + W1_BLKS + W2_BLKS)

#define TLD 36                       // tile row stride (floats), 16B-aligned

__global__ void __launch_bounds__(256)
prep_kernel(const float* __restrict__ feat,
            const float* __restrict__ W1,
            const float* __restrict__ W2,
            const float* __restrict__ grid,
            const float* __restrict__ anc,
            const float* __restrict__ bboxes,
            const int* __restrict__ pos,
            const int* __restrict__ neg,
            float* __restrict__ out) {
    const int bid = blockIdx.x;
    const int t   = threadIdx.x;

    if (bid < TR_BLKS) {
        // ---- transpose + bf16 split ----
        __shared__ float tile[2][64][TLD];
        __shared__ unsigned char sflag[32];
        const int pt = bid % 25;
        const int b  = bid / 25;
        const int p0 = pt * 32;

        // inline flag scan (replaces mark_kernel)
        if (t < 32) sflag[t] = 0;
        __syncthreads();
#pragma unroll 4
        for (int i = t; i < MTOT; i += 256) {
            int idx = (i < M_) ? pos[i] : neg[i - M_];
            int p  = idx % HW;
            int bb = idx / (HW * A_);
            int d  = p - p0;
            if (bb == b && ((unsigned)d < 32u)) sflag[d] = 1;
        }

        const uint32_t tb0 = smem_u32(&tile[0][0][0]);
        const uint32_t tb1 = smem_u32(&tile[1][0][0]);
        const float* fb = feat + (size_t)b * CIN * HW;

        // cp.async issue for one k-tile: 512 x 16B, 2 per thread
        const int kk0 = t >> 3;            // k row (0..31) phase 0
        const int j4  = (t & 7) * 4;       // p offset
        // issue kt=0
        {
#pragma unroll
            for (int h = 0; h < 2; h++) {
                int kk = kk0 + h * 32;
                int p  = p0 + j4;
                uint32_t dst = tb0 + (kk * TLD + j4) * 4;
                if (p + 3 < HW) {
                    cpa16(dst, fb + (size_t)kk * HW + p);
                } else {
                    *(float4*)((char*)&tile[0][0][0] + (kk * TLD + j4) * 4)
                        = make_float4(0.f, 0.f, 0.f, 0.f);
                }
            }
            CP_COMMIT();
        }
        __syncthreads();   // flags + first issue ordering

        const int pr = t >> 3;        // store-phase p (0..31)
        const int gq = t & 7;         // store-phase k-group (0..7)
        const bool dostore = sflag[pr];

        for (int kt = 0; kt < 20; kt++) {
            // prefetch kt+1
            if (kt + 1 < 20) {
                uint32_t tbn = (kt & 1) ? tb0 : tb1;
                float* tpn = (kt & 1) ? &tile[0][0][0] : &tile[1][0][0];
                const int k0n = (kt + 1) * 64;
#pragma unroll
                for (int h = 0; h < 2; h++) {
                    int kk = kk0 + h * 32;
                    int p  = p0 + j4;
                    if (p + 3 < HW) {
                        cpa16(tbn + (kk * TLD + j4) * 4,
                              fb + (size_t)(k0n + kk) * HW + p);
                    } else {
                        *(float4*)((char*)tpn + (kk * TLD + j4) * 4)
                            = make_float4(0.f, 0.f, 0.f, 0.f);
                    }
                }
                CP_COMMIT();
                CP_WAIT1();
            } else {
                CP_WAIT0();
            }
            __syncthreads();

            if (dostore) {
                const float (*tl)[TLD] = tile[kt & 1];
                const int k0 = kt * 64;
                size_t base = (size_t)(b * HW + p0 + pr) * CIN + k0 + gq * 8;
                uint32_t hiw[4], low[4];
#pragma unroll
                for (int i2 = 0; i2 < 4; i2++) {
                    float v0 = tl[gq * 8 + i2 * 2 + 0][pr];
                    float v1 = tl[gq * 8 + i2 * 2 + 1][pr];
                    __nv_bfloat16 h0 = __float2bfloat16(v0);
                    __nv_bfloat16 h1 = __float2bfloat16(v1);
                    hiw[i2] = PK(h0, h1);
                    low[i2] = PK(__float2bfloat16(v0 - __bfloat162float(h0)),
                                 __float2bfloat16(v1 - __bfloat162float(h1)));
                }
                *(uint4*)&g_fT_hi[base] = make_uint4(hiw[0], hiw[1], hiw[2], hiw[3]);
                *(uint4*)&g_fT_lo[base] = make_uint4(low[0], low[1], low[2], low[3]);
            }
            __syncthreads();
        }
        return;
    }

    if (bid < TR_BLKS + IOU_BLKS) {
        // ---- IoU ----
        __shared__ float s_x1[64], s_y1[64], s_x2[64], s_y2[64], s_sb[64];
        int r  = bid - TR_BLKS;
        int bx = r % 56;
        int b  = r / 56;

        if (t < 64) {
            const float* bb = bboxes + ((size_t)b * 64 + t) * 5;
            float x1 = bb[0], y1 = bb[1], x2 = bb[2], y2 = bb[3];
            s_x1[t] = x1; s_y1[t] = y1; s_x2[t] = x2; s_y2[t] = y2;
            float sb = (x2 - x1) * (y2 - y1);
            s_sb[t] = (x1 < 0.0f) ? 0.0f : sb;
        }
        __syncthreads();

        const int n4   = (t & 15) * 4;
        const int jrow = t >> 4;
        const int j0   = bx * 128;

        float bx1[4], by1[4], bx2[4], by2[4], sb4[4];
#pragma unroll
        for (int i = 0; i < 4; i++) {
            bx1[i] = s_x1[n4 + i]; by1[i] = s_y1[n4 + i];
            bx2[i] = s_x2[n4 + i]; by2[i] = s_y2[n4 + i];
            sb4[i] = s_sb[n4 + i];
        }

#pragma unroll
        for (int it = 0; it < 8; it++) {
            int j = j0 + it * 16 + jrow;
            if (j >= AHW) break;
            int a  = j / HW;
            int rr = j - a * HW;
            int h  = rr / WW;
            int w  = rr - h * WW;
            float cx = grid[(((size_t)b * HH + h) * WW + w) * 2 + 0];
            float cy = grid[(((size_t)b * HH + h) * WW + w) * 2 + 1];
            float hw2 = anc[a * 2 + 0] * 0.5f;
            float hh2 = anc[a * 2 + 1] * 0.5f;
            float px1 = cx - hw2, py1 = cy - hh2, px2 = cx + hw2, py2 = cy + hh2;
            float sp  = (px2 - px1) * (py2 - py1);

            float4 v;
            float* vp = &v.x;
#pragma unroll
            for (int i = 0; i < 4; i++) {
                float ix1 = fmaxf(px1, bx1[i]);
                float iy1 = fmaxf(py1, by1[i]);
                float ix2 = fminf(px2, bx2[i]);
                float iy2 = fminf(py2, by2[i]);
                float si  = fmaxf(ix2 - ix1, 0.0f) * fmaxf(iy2 - iy1, 0.0f);
                float su  = sp + sb4[i] - si;
                vp[i] = (su <= 0.0f || sp <= 0.0f || sb4[i] <= 0.0f)
                        ? 0.0f : fmaxf(si / (su + 1e-8f), 0.0f);
            }
            *(float4*)&out[OFF_IOU + ((size_t)b * AHW + j) * 64 + n4] = v;
        }
        return;
    }

    if (bid < TR_BLKS + IOU_BLKS + W1_BLKS) {
        int i4 = (bid - TR_BLKS - IOU_BLKS) * 256 + t;
        const float4 v = ((const float4*)W1)[i4];
        __nv_bfloat16 h0 = __float2bfloat16(v.x), h1 = __float2bfloat16(v.y);
        __nv_bfloat16 h2 = __float2bfloat16(v.z), h3 = __float2bfloat16(v.w);
        ((uint2*)g_W1hi)[i4] = make_uint2(PK(h0, h1), PK(h2, h3));
        ((uint2*)g_W1lo)[i4] = make_uint2(
            PK(__float2bfloat16(v.x - __bfloat162float(h0)),
               __float2bfloat16(v.y - __bfloat162float(h1))),
            PK(__float2bfloat16(v.z - __bfloat162float(h2)),
               __float2bfloat16(v.w - __bfloat162float(h3))));
        return;
    }

    {
        int i4 = (bid - TR_BLKS - IOU_BLKS - W1_BLKS) * 256 + t;
        if (i4 < (65 * HID) / 4) {
            const float4 v = ((const float4*)W2)[i4];
            __nv_bfloat16 h0 = __float2bfloat16(v.x), h1 = __float2bfloat16(v.y);
            __nv_bfloat16 h2 = __float2bfloat16(v.z), h3 = __float2bfloat16(v.w);
            ((uint2*)g_W2hi)[i4] = make_uint2(PK(h0, h1), PK(h2, h3));
            ((uint2*)g_W2lo)[i4] = make_uint2(
                PK(__float2bfloat16(v.x - __bfloat162float(h0)),
                   __float2bfloat16(v.y - __bfloat162float(h1))),
                PK(__float2bfloat16(v.z - __bfloat162float(h2)),
                   __float2bfloat16(v.w - __bfloat162float(h3))));
        }
    }
}

// ---------------------------------------------------------------------------
// Kernel 2: gathered WMMA GEMM + fused head epilogue (unchanged from R8)
// ---------------------------------------------------------------------------
#define LDA 72
#define LDB 72
#define NCHUNK 20
#define SA_HI 0
#define SA_LO (64 * LDA)
#define SB_HI (2 * 64 * LDA)
#define SB_LO (2 * 64 * LDA + 128 * LDB)
#define STAGE_ELEMS (2 * 64 * LDA + 2 * 128 * LDB)   // 27648
#define NSTAGE 3
#define SMEM_GEMM_BYTES (NSTAGE * STAGE_ELEMS * 2)   // 165888

#define LDS_STAGE 132
#define H_HI_OFF  34816
#define H_LO_OFF  52224
#define LDH       136
#define W2HI_OFF  69632
#define W2LO_OFF  91392
#define LDW2      136
#define ST2_OFF   113152
#define LDS2      84

extern __shared__ __nv_bfloat16 smem_g[];

__device__ __forceinline__ void gemm_issue(uint32_t sbase, int k0,
                                           const int* __restrict__ srow, int t) {
    {
        int row = t >> 3;
        int j   = t & 7;
        size_t src = (size_t)srow[row] * CIN + k0 + j * 8;
        cpa16(sbase + (SA_HI + row * LDA + j * 8) * 2, g_fT_hi + src);
        cpa16(sbase + (SA_LO + row * LDA + j * 8) * 2, g_fT_lo + src);
    }
#pragma unroll
    for (int h = 0; h < 2; h++) {
        int q = t + h * 512;
        int n = q >> 3;
        int j = q & 7;
        size_t src = (size_t)n * CIN + k0 + j * 8;
        cpa16(sbase + (SB_HI + n * LDB + j * 8) * 2, g_W1hi + src);
        cpa16(sbase + (SB_LO + n * LDB + j * 8) * 2, g_W1lo + src);
    }
}

__global__ void __launch_bounds__(512, 1)
gemm_wmma_kernel(const int* __restrict__ pos,
                 const int* __restrict__ neg,
                 const float* __restrict__ b1,
                 const float* __restrict__ b2,
                 float* __restrict__ out) {
    __shared__ int srow[64];
    __shared__ int sanc[64];

    const int t   = threadIdx.x;
    const int wid = t >> 5;
    const int i0  = blockIdx.x * 64;
    const bool isneg = (i0 >= M_);

    if (t < 64) {
        int gi  = i0 + t;
        int idx = (gi < M_) ? pos[gi] : neg[gi - M_];
        int p   = idx % HW;
        int ba  = idx / HW;
        srow[t] = (ba / A_) * HW + p;
        sanc[t] = ba % A_;
    }
    __syncthreads();

    const uint32_t sb = smem_u32(smem_g);

    const int wr = wid >> 2;
    const int wc = wid & 3;

    wmma::fragment<wmma::accumulator, 16, 16, 16, float> acc[2];
#pragma unroll
    for (int nt = 0; nt < 2; nt++) wmma::fill_fragment(acc[nt], 0.0f);

    gemm_issue(sb, 0, srow, t);
    CP_COMMIT();
    gemm_issue(sb + STAGE_ELEMS * 2, 64, srow, t);
    CP_COMMIT();

    int stg = 0;
    for (int c = 0; c < NCHUNK; c++) {
        if (c + 2 < NCHUNK) {
            int s2 = stg + 2; if (s2 >= NSTAGE) s2 -= NSTAGE;
            gemm_issue(sb + s2 * STAGE_ELEMS * 2, (c + 2) * 64, srow, t);
            CP_COMMIT();
            CP_WAIT2();
        } else if (c + 1 < NCHUNK) {
            CP_WAIT1();
        } else {
            CP_WAIT0();
        }
        __syncthreads();

        const __nv_bfloat16* buf = smem_g + stg * STAGE_ELEMS;
#pragma unroll
        for (int ks = 0; ks < 4; ks++) {
            wmma::fragment<wmma::matrix_a, 16, 16, 16, __nv_bfloat16, wmma::row_major> a_hi, a_lo;
            wmma::load_matrix_sync(a_hi, buf + SA_HI + (wr * 16) * LDA + ks * 16, LDA);
            wmma::load_matrix_sync(a_lo, buf + SA_LO + (wr * 16) * LDA + ks * 16, LDA);
#pragma unroll
            for (int nt = 0; nt < 2; nt++) {
                int n = wc * 32 + nt * 16;
                wmma::fragment<wmma::matrix_b, 16, 16, 16, __nv_bfloat16, wmma::col_major> b_hi, b_lo;
                wmma::load_matrix_sync(b_hi, buf + SB_HI + n * LDB + ks * 16, LDB);
                wmma::load_matrix_sync(b_lo, buf + SB_LO + n * LDB + ks * 16, LDB);
                wmma::mma_sync(acc[nt], a_hi, b_hi, acc[nt]);
                wmma::mma_sync(acc[nt], a_hi, b_lo, acc[nt]);
                wmma::mma_sync(acc[nt], a_lo, b_hi, acc[nt]);
            }
        }
        __syncthreads();
        if (++stg == NSTAGE) stg = 0;
    }

    // epilogue 1: accum -> stage (fp32)
    float* stage = (float*)smem_g;
#pragma unroll
    for (int nt = 0; nt < 2; nt++) {
        wmma::store_matrix_sync(&stage[(wr * 16) * LDS_STAGE + wc * 32 + nt * 16],
                                acc[nt], LDS_STAGE, wmma::mem_row_major);
    }
    __syncthreads();

    // epilogue 2: h -> bf16 hi/lo; W2 -> smem
    __nv_bfloat16* hhi  = (__nv_bfloat16*)((char*)smem_g + H_HI_OFF);
    __nv_bfloat16* hlo  = (__nv_bfloat16*)((char*)smem_g + H_LO_OFF);
    __nv_bfloat16* w2hi = (__nv_bfloat16*)((char*)smem_g + W2HI_OFF);
    __nv_bfloat16* w2lo = (__nv_bfloat16*)((char*)smem_g + W2LO_OFF);

    for (int i = t; i < 64 * 32; i += 512) {
        int row = i >> 5;
        int c4  = (i & 31) * 4;
        float4 v = *(float4*)&stage[row * LDS_STAGE + c4];
        v.x += b1[c4 + 0]; v.y += b1[c4 + 1]; v.z += b1[c4 + 2]; v.w += b1[c4 + 3];
        v.x = (v.x > 0.f) ? v.x : 0.01f * v.x;
        v.y = (v.y > 0.f) ? v.y : 0.01f * v.y;
        v.z = (v.z > 0.f) ? v.z : 0.01f * v.z;
        v.w = (v.w > 0.f) ? v.w : 0.01f * v.w;
        __nv_bfloat16 h0 = __float2bfloat16(v.x), h1 = __float2bfloat16(v.y);
        __nv_bfloat16 h2 = __float2bfloat16(v.z), h3 = __float2bfloat16(v.w);
        *(uint2*)&hhi[row * LDH + c4] = make_uint2(PK(h0, h1), PK(h2, h3));
        *(uint2*)&hlo[row * LDH + c4] = make_uint2(
            PK(__float2bfloat16(v.x - __bfloat162float(h0)),
               __float2bfloat16(v.y - __bfloat162float(h1))),
            PK(__float2bfloat16(v.z - __bfloat162float(h2)),
               __float2bfloat16(v.w - __bfloat162float(h3))));
    }
    for (int q = t; q < 80 * 16; q += 512) {
        int n = q >> 4;
        int j = q & 15;
        *(uint4*)&w2hi[n * LDW2 + j * 8] = *(const uint4*)&g_W2hi[n * HID + j * 8];
        *(uint4*)&w2lo[n * LDW2 + j * 8] = *(const uint4*)&g_W2lo[n * HID + j * 8];
    }
    __syncthreads();

    // epilogue 3: D2[64 x 80] = H @ W2^T
    float* stage2 = (float*)((char*)smem_g + ST2_OFF);
    const int ntile = isneg ? 12 : 20;
    for (int tid = wid; tid < ntile; tid += 16) {
        int wr2 = tid & 3;
        int wc2 = tid >> 2;
        wmma::fragment<wmma::accumulator, 16, 16, 16, float> acc2;
        wmma::fill_fragment(acc2, 0.0f);
#pragma unroll
        for (int ks = 0; ks < 8; ks++) {
            wmma::fragment<wmma::matrix_a, 16, 16, 16, __nv_bfloat16, wmma::row_major> a_hi, a_lo;
            wmma::load_matrix_sync(a_hi, &hhi[(wr2 * 16) * LDH + ks * 16], LDH);
            wmma::load_matrix_sync(a_lo, &hlo[(wr2 * 16) * LDH + ks * 16], LDH);
            wmma::fragment<wmma::matrix_b, 16, 16, 16, __nv_bfloat16, wmma::col_major> b_hi, b_lo;
            wmma::load_matrix_sync(b_hi, &w2hi[(wc2 * 16) * LDW2 + ks * 16], LDW2);
            wmma::load_matrix_sync(b_lo, &w2lo[(wc2 * 16) * LDW2 + ks * 16], LDW2);
            wmma::mma_sync(acc2, a_hi, b_hi, acc2);
            wmma::mma_sync(acc2, a_hi, b_lo, acc2);
            wmma::mma_sync(acc2, a_lo, b_hi, acc2);
        }
        wmma::store_matrix_sync(&stage2[(wr2 * 16) * LDS2 + wc2 * 16],
                                acc2, LDS2, wmma::mem_row_major);
    }
    __syncthreads();

    // epilogue 4: output mapping
    if (!isneg) {
        for (int e = t; e < 64 * 25; e += 512) {
            int row = e / 25;
            int q   = e - row * 25;
            int gi  = i0 + row;
            int a   = sanc[row];
            if (q == 0) {
                int n = 5 * a;
                float s = stage2[row * LDS2 + n] + b2[n];
                out[OFF_CONF + gi] = sigmoidf_(s);
            } else if (q <= 4) {
                int n = 5 * a + q;
                float s = stage2[row * LDS2 + n] + b2[n];
                out[OFF_OFFS + gi * 4 + (q - 1)] = (q <= 2) ? (sigmoidf_(s) - 0.5f) : s;
            } else {
                int n = 40 + q;
                float s = stage2[row * LDS2 + n] + b2[n];
                out[OFF_CLASS + gi * 20 + (q - 5)] = s;
            }
        }
    } else {
        if (t < 64) {
            int gi = i0 + t;
            int n  = 5 * sanc[t];
            float s = stage2[t * LDS2 + n] + b2[n];
            out[OFF_CONF + gi] = sigmoidf_(s);
        }
    }
}

// ---------------------------------------------------------------------------
// Launch
// ---------------------------------------------------------------------------
extern "C" void kernel_launch(void* const* d_in, const int* in_sizes, int n_in,
                              void* d_out, int out_size) {
    const float* features = (const float*)d_in[0];
    const float* grid     = (const float*)d_in[1];
    const float* anc      = (const float*)d_in[2];
    const float* bboxes   = (const float*)d_in[3];
    const int*   pos      = (const int*)d_in[4];
    const int*   neg      = (const int*)d_in[5];
    const float* W1       = (const float*)d_in[6];
    const float* b1       = (const float*)d_in[7];
    const float* W2       = (const float*)d_in[8];
    const float* b2       = (const float*)d_in[9];
    float* out = (float*)d_out;

    prep_kernel<<<PREP_BLKS, 256>>>(features, W1, W2, grid, anc, bboxes,
                                    pos, neg, out);

    cudaFuncSetAttribute(gemm_wmma_kernel,
                         cudaFuncAttributeMaxDynamicSharedMemorySize,
                         SMEM_GEMM_BYTES);
    gemm_wmma_kernel<<<MTOT / 64, 512, SMEM_GEMM_BYTES>>>(pos, neg, b1, b2, out);
}